// round 10
// baseline (speedup 1.0000x reference)
#include <cuda_runtime.h>
#include <cuda_bf16.h>
#include <cstdint>

// Tree-RNN, bf16x3-split GEMMs on mma.sync tensor cores.
// - Leaf + mids (m>=1024): R5-exact 128x64 gemm64 (4-stage ring, occ 2).
// - Tail (m<=512, 10 levels): ONE persistent kernel, 128 CTAs, global
//   barrier between levels (cp.async.cg input path = L1-bypass, safe).

// ---------------- device scratch (no allocation allowed) ----------------
__device__ __nv_bfloat16 g_leaf_hi[8192ull * 4096];
__device__ __nv_bfloat16 g_leaf_lo[8192ull * 4096];
__device__ __nv_bfloat16 g_We_hi[512 * 4096];
__device__ __nv_bfloat16 g_We_lo[512 * 4096];
__device__ __nv_bfloat16 g_Wc_hi[512 * 1024];
__device__ __nv_bfloat16 g_Wc_lo[512 * 1024];
__device__ __nv_bfloat16 g_hA[8192 * 512], g_lA[8192 * 512];
__device__ __nv_bfloat16 g_hB[4096 * 512], g_lB[4096 * 512];
__device__ unsigned g_bar_count = 0;
__device__ unsigned g_bar_flag  = 0;

// ---------------- PTX helpers ----------------
__device__ __forceinline__ void mma_bf16(float c[4], const uint32_t a[4],
                                         const uint32_t b0, const uint32_t b1) {
    asm volatile(
        "mma.sync.aligned.m16n8k16.row.col.f32.bf16.bf16.f32 "
        "{%0,%1,%2,%3}, {%4,%5,%6,%7}, {%8,%9}, {%0,%1,%2,%3};\n"
        : "+f"(c[0]), "+f"(c[1]), "+f"(c[2]), "+f"(c[3])
        : "r"(a[0]), "r"(a[1]), "r"(a[2]), "r"(a[3]), "r"(b0), "r"(b1));
}
__device__ __forceinline__ void cp16(uint32_t dst, const void* src, bool p) {
    asm volatile("cp.async.cg.shared.global [%0], [%1], 16, %2;"
                 :: "r"(dst), "l"(src), "r"(p ? 16 : 0));
}
__device__ __forceinline__ void cp_commit() {
    asm volatile("cp.async.commit_group;");
}
template <int N> __device__ __forceinline__ void cp_wait() {
    asm volatile("cp.async.wait_group %0;" :: "n"(N));
}
__device__ __forceinline__ void ldsm4(uint32_t r[4], uint32_t a) {
    asm volatile("ldmatrix.sync.aligned.m8n8.x4.shared.b16 {%0,%1,%2,%3}, [%4];"
                 : "=r"(r[0]), "=r"(r[1]), "=r"(r[2]), "=r"(r[3]) : "r"(a));
}
__device__ __forceinline__ uint32_t pack_bf2(__nv_bfloat16 a, __nv_bfloat16 b) {
    __nv_bfloat162 t{a, b};
    return *reinterpret_cast<uint32_t*>(&t);
}

// ---------------- fp32 -> bf16 hi/lo split (streaming) ----------------
__global__ void split_kernel(const float4* __restrict__ src,
                             uint2* __restrict__ hi, uint2* __restrict__ lo,
                             int n4)
{
    int i = blockIdx.x * blockDim.x + threadIdx.x;
    const int stride = gridDim.x * blockDim.x;
    for (; i < n4; i += stride) {
        float4 v = src[i];
        __nv_bfloat16 h0 = __float2bfloat16(v.x), h1 = __float2bfloat16(v.y);
        __nv_bfloat16 h2 = __float2bfloat16(v.z), h3 = __float2bfloat16(v.w);
        uint2 H, L;
        H.x = pack_bf2(h0, h1);
        H.y = pack_bf2(h2, h3);
        L.x = pack_bf2(__float2bfloat16(v.x - __bfloat162float(h0)),
                       __float2bfloat16(v.y - __bfloat162float(h1)));
        L.y = pack_bf2(__float2bfloat16(v.z - __bfloat162float(h2)),
                       __float2bfloat16(v.w - __bfloat162float(h3)));
        hi[i] = H;
        lo[i] = L;
    }
}

// ============================================================================
// gemm64: 128x64 tile, BK=32, 4-stage ring, prefetch distance 3 (R5-exact).
// ============================================================================
#define A_T1 16384
#define STAGE1 24576
#define SMEM1 (4 * STAGE1)    // 98304

__global__ __launch_bounds__(256, 2)
void gemm64(const __nv_bfloat16* __restrict__ Ahi,
            const __nv_bfloat16* __restrict__ Alo,
            const __nv_bfloat16* __restrict__ Whi,
            const __nv_bfloat16* __restrict__ Wlo,
            const float* __restrict__ bias,
            __nv_bfloat16* __restrict__ Chi,
            __nv_bfloat16* __restrict__ Clo,
            int M, int N, int K)
{
    extern __shared__ __align__(1024) char smem[];
    const uint32_t sbase = (uint32_t)__cvta_generic_to_shared(smem);

    const int tid  = threadIdx.x;
    const int lane = tid & 31;
    const int wid  = tid >> 5;
    const int wm   = (wid & 3) * 32;
    const int wn   = (wid >> 2) * 32;
    const int bm   = blockIdx.y * 128;
    const int bn   = blockIdx.x * 64;

    const int lr8   = lane & 7;
    const int g     = lane >> 3;
    const int mrow  = (g & 1) * 8;
    const int kcolB = (g >> 1) * 16;

    uint32_t aRow[2], aXm[2], bRow[2], bXm[2];
    #pragma unroll
    for (int mi = 0; mi < 2; mi++) {
        const uint32_t rB = (uint32_t)(wm + mi * 16 + mrow + lr8) * 128;
        aRow[mi] = rB;
        aXm[mi]  = (rB >> 3) & 0x70;
    }
    #pragma unroll
    for (int p = 0; p < 2; p++) {
        const uint32_t rB = (uint32_t)(wn + p * 16 + mrow + lr8) * 128;
        bRow[p] = A_T1 + rB;
        bXm[p]  = (rB >> 3) & 0x70;
    }

    float acc[2][4][4];
    #pragma unroll
    for (int i = 0; i < 2; i++)
        #pragma unroll
        for (int j = 0; j < 4; j++)
            #pragma unroll
            for (int v = 0; v < 4; v++) acc[i][j][v] = 0.f;

    const int nT = K / 32;

    auto stage = [&](int lt) {
        const uint32_t sb = sbase + (uint32_t)(lt & 3) * STAGE1;
        const int k0 = lt * 32;
        #pragma unroll
        for (int i = 0; i < 4; i++) {
            const int lin = tid + i * 256;
            const int r = lin >> 3;
            const int c = lin & 7;
            const uint32_t off = (uint32_t)r * 128 + (uint32_t)c * 16;
            const uint32_t sw = off ^ ((off >> 3) & 0x70);
            const bool pa = (bm + r) < M;
            const __nv_bfloat16* src = (c < 4) ? Ahi : Alo;
            cp16(sb + sw, src + (size_t)(bm + r) * K + k0 + (c & 3) * 8, pa);
        }
        #pragma unroll
        for (int i = 0; i < 2; i++) {
            const int lin = tid + i * 256;
            const int r = lin >> 3;
            const int c = lin & 7;
            const uint32_t off = (uint32_t)r * 128 + (uint32_t)c * 16;
            const uint32_t sw = off ^ ((off >> 3) & 0x70);
            const __nv_bfloat16* src = (c < 4) ? Whi : Wlo;
            cp16(sb + A_T1 + sw, src + (size_t)(bn + r) * K + k0 + (c & 3) * 8, true);
        }
        cp_commit();
    };

    stage(0);
    stage(1);
    stage(2);

    for (int kt = 0; kt < nT; kt++) {
        if (kt + 2 <= nT - 1)      cp_wait<2>();
        else if (kt + 1 <= nT - 1) cp_wait<1>();
        else                       cp_wait<0>();
        __syncthreads();
        if (kt + 3 < nT) stage(kt + 3);

        const uint32_t s0 = sbase + (uint32_t)(kt & 3) * STAGE1;

        #pragma unroll
        for (int ks = 0; ks < 32; ks += 16) {
            const uint32_t colH = (uint32_t)(ks * 2) + kcolB;
            const uint32_t colL = 64u + (uint32_t)(ks * 2) + kcolB;
            uint32_t ah[2][4], al[2][4], bh[2][4], bl[2][4];
            #pragma unroll
            for (int mi = 0; mi < 2; mi++) {
                ldsm4(ah[mi], s0 + aRow[mi] + (colH ^ aXm[mi]));
                ldsm4(al[mi], s0 + aRow[mi] + (colL ^ aXm[mi]));
            }
            #pragma unroll
            for (int p = 0; p < 2; p++) {
                ldsm4(bh[p], s0 + bRow[p] + (colH ^ bXm[p]));
                ldsm4(bl[p], s0 + bRow[p] + (colL ^ bXm[p]));
            }
            #pragma unroll
            for (int mi = 0; mi < 2; mi++)
                #pragma unroll
                for (int ni = 0; ni < 4; ni++) {
                    const int p = ni >> 1, q = ni & 1;
                    mma_bf16(acc[mi][ni], ah[mi], bh[p][q], bh[p][q + 2]);
                    mma_bf16(acc[mi][ni], ah[mi], bl[p][q], bl[p][q + 2]);
                    mma_bf16(acc[mi][ni], al[mi], bh[p][q], bh[p][q + 2]);
                }
        }
    }

    const int lq = (lane & 3) * 2;
    const int lr = lane >> 2;
    #pragma unroll
    for (int mi = 0; mi < 2; mi++) {
        #pragma unroll
        for (int ni = 0; ni < 4; ni++) {
            const int m0 = bm + wm + mi * 16 + lr;
            const int n  = bn + wn + ni * 8 + lq;
            const float bv0 = __ldg(bias + n), bv1 = __ldg(bias + n + 1);
            #pragma unroll
            for (int h = 0; h < 2; h++) {
                const int m = m0 + h * 8;
                if (m < M) {
                    float x0 = fmaxf(acc[mi][ni][2 * h]     + bv0, 0.f);
                    float x1 = fmaxf(acc[mi][ni][2 * h + 1] + bv1, 0.f);
                    __nv_bfloat16 h0 = __float2bfloat16(x0);
                    __nv_bfloat16 h1 = __float2bfloat16(x1);
                    __nv_bfloat16 l0 = __float2bfloat16(x0 - __bfloat162float(h0));
                    __nv_bfloat16 l1 = __float2bfloat16(x1 - __bfloat162float(h1));
                    *reinterpret_cast<uint32_t*>(Chi + (size_t)m * N + n) = pack_bf2(h0, h1);
                    *reinterpret_cast<uint32_t*>(Clo + (size_t)m * N + n) = pack_bf2(l0, l1);
                }
            }
        }
    }
}

// ============================================================================
// tail_kernel: persistent, 128 CTAs x 128 threads. Levels m=512..1, global
// barrier between levels. Each CTA computes one 32x64 tile per level
// (gemm_small structure, full K=1024, 3-stage ring).
// ============================================================================
#define NCTA_TAIL 128
#define A_T3 4096
#define STAGE3 12288
#define SMEM3 (3 * STAGE3)    // 36864

__device__ __forceinline__ void grid_barrier() {
    __syncthreads();
    if (threadIdx.x == 0) {
        volatile unsigned* flag = &g_bar_flag;
        const unsigned f = *flag;
        __threadfence();
        const unsigned my = atomicAdd(&g_bar_count, 1u);
        if (my == NCTA_TAIL - 1) {
            g_bar_count = 0;
            __threadfence();
            atomicAdd(&g_bar_flag, 1u);
        } else {
            while (*flag == f) { __nanosleep(64); }
        }
    }
    __syncthreads();
}

__global__ __launch_bounds__(128, 1)
void tail_kernel(const __nv_bfloat16* __restrict__ inH0,
                 const __nv_bfloat16* __restrict__ inL0,
                 __nv_bfloat16* __restrict__ outH0,
                 __nv_bfloat16* __restrict__ outL0,
                 const __nv_bfloat16* __restrict__ Whi,
                 const __nv_bfloat16* __restrict__ Wlo,
                 const float* __restrict__ bias)
{
    extern __shared__ __align__(1024) char smem[];
    const uint32_t sbase = (uint32_t)__cvta_generic_to_shared(smem);

    const int tid  = threadIdx.x;
    const int lane = tid & 31;
    const int wid  = tid >> 5;
    const int wm   = (wid & 1) * 16;
    const int wn   = (wid >> 1) * 32;
    constexpr int N = 512, K = 1024;

    const int lr8   = lane & 7;
    const int g     = lane >> 3;
    const int mrow  = (g & 1) * 8;
    const int kcolB = (g >> 1) * 16;

    uint32_t aRowB, aXm, bRow[2], bXm[2];
    {
        const uint32_t rB = (uint32_t)(wm + mrow + lr8) * 128;
        aRowB = rB;
        aXm   = (rB >> 3) & 0x70;
    }
    #pragma unroll
    for (int p = 0; p < 2; p++) {
        const uint32_t rB = (uint32_t)(wn + p * 16 + mrow + lr8) * 128;
        bRow[p] = A_T3 + rB;
        bXm[p]  = (rB >> 3) & 0x70;
    }

    const __nv_bfloat16* inH = inH0;
    const __nv_bfloat16* inL = inL0;
    __nv_bfloat16* outH = outH0;
    __nv_bfloat16* outL = outL0;

    for (int m = 512; m >= 1; m >>= 1) {
        const int tilesM = (m + 31) / 32;
        const int tiles  = tilesM * 8;
        if ((int)blockIdx.x < tiles) {
            const int bm = ((int)blockIdx.x / 8) * 32;
            const int bn = ((int)blockIdx.x % 8) * 64;

            float acc[4][4];
            #pragma unroll
            for (int j = 0; j < 4; j++)
                #pragma unroll
                for (int v = 0; v < 4; v++) acc[j][v] = 0.f;

            const int nT = K / 32;    // 32

            auto stage = [&](int lt) {
                const uint32_t sb = sbase + (uint32_t)(lt % 3) * STAGE3;
                const int k0 = lt * 32;
                #pragma unroll
                for (int i = 0; i < 2; i++) {             // A: 32 rows
                    const int lin = tid + i * 128;
                    const int r = lin >> 3;
                    const int c = lin & 7;
                    const uint32_t off = (uint32_t)r * 128 + (uint32_t)c * 16;
                    const uint32_t sw = off ^ ((off >> 3) & 0x70);
                    const bool pa = (bm + r) < m;
                    const __nv_bfloat16* src = (c < 4) ? inH : inL;
                    cp16(sb + sw, src + (size_t)(bm + r) * K + k0 + (c & 3) * 8, pa);
                }
                #pragma unroll
                for (int i = 0; i < 4; i++) {             // B: 64 rows
                    const int lin = tid + i * 128;
                    const int r = lin >> 3;
                    const int c = lin & 7;
                    const uint32_t off = (uint32_t)r * 128 + (uint32_t)c * 16;
                    const uint32_t sw = off ^ ((off >> 3) & 0x70);
                    const __nv_bfloat16* src = (c < 4) ? Whi : Wlo;
                    cp16(sb + A_T3 + sw, src + (size_t)(bn + r) * K + k0 + (c & 3) * 8, true);
                }
                cp_commit();
            };

            stage(0);
            stage(1);

            for (int kt = 0; kt < nT; kt++) {
                if (kt + 1 < nT) cp_wait<1>();
                else             cp_wait<0>();
                __syncthreads();
                if (kt + 2 < nT) stage(kt + 2);

                const uint32_t s0 = sbase + (uint32_t)(kt % 3) * STAGE3;

                #pragma unroll
                for (int ks = 0; ks < 32; ks += 16) {
                    const uint32_t colH = (uint32_t)(ks * 2) + kcolB;
                    const uint32_t colL = 64u + (uint32_t)(ks * 2) + kcolB;
                    uint32_t ah[4], al[4], bh[2][4], bl[2][4];
                    ldsm4(ah, s0 + aRowB + (colH ^ aXm));
                    ldsm4(al, s0 + aRowB + (colL ^ aXm));
                    #pragma unroll
                    for (int p = 0; p < 2; p++) {
                        ldsm4(bh[p], s0 + bRow[p] + (colH ^ bXm[p]));
                        ldsm4(bl[p], s0 + bRow[p] + (colL ^ bXm[p]));
                    }
                    #pragma unroll
                    for (int ni = 0; ni < 4; ni++) {
                        const int p = ni >> 1, q = ni & 1;
                        mma_bf16(acc[ni], ah, bh[p][q], bh[p][q + 2]);
                        mma_bf16(acc[ni], ah, bl[p][q], bl[p][q + 2]);
                        mma_bf16(acc[ni], al, bh[p][q], bh[p][q + 2]);
                    }
                }
            }

            // fused epilogue: bias + relu + hi/lo split
            const int lq = (lane & 3) * 2;
            const int lr = lane >> 2;
            #pragma unroll
            for (int ni = 0; ni < 4; ni++) {
                const int m0 = bm + wm + lr;
                const int n  = bn + wn + ni * 8 + lq;
                const float bv0 = __ldg(bias + n), bv1 = __ldg(bias + n + 1);
                #pragma unroll
                for (int h = 0; h < 2; h++) {
                    const int mm = m0 + h * 8;
                    if (mm < m) {
                        float x0 = fmaxf(acc[ni][2 * h]     + bv0, 0.f);
                        float x1 = fmaxf(acc[ni][2 * h + 1] + bv1, 0.f);
                        __nv_bfloat16 h0 = __float2bfloat16(x0);
                        __nv_bfloat16 h1 = __float2bfloat16(x1);
                        __nv_bfloat16 l0 = __float2bfloat16(x0 - __bfloat162float(h0));
                        __nv_bfloat16 l1 = __float2bfloat16(x1 - __bfloat162float(h1));
                        *reinterpret_cast<uint32_t*>(outH + (size_t)mm * N + n) = pack_bf2(h0, h1);
                        *reinterpret_cast<uint32_t*>(outL + (size_t)mm * N + n) = pack_bf2(l0, l1);
                    }
                }
            }
        }
        grid_barrier();
        // swap buffers
        const __nv_bfloat16* tH = inH; inH = outH; outH = const_cast<__nv_bfloat16*>(tH);
        const __nv_bfloat16* tL = inL; inL = outL; outL = const_cast<__nv_bfloat16*>(tL);
    }
}

// Root projection
__global__ void proj_kernel(const __nv_bfloat16* __restrict__ hhi,
                            const __nv_bfloat16* __restrict__ hlo,
                            const float* __restrict__ Wp,
                            const float* __restrict__ bp,
                            float* __restrict__ out)
{
    const int w    = threadIdx.x >> 5;
    const int lane = threadIdx.x & 31;
    float s = 0.f;
    for (int k = lane; k < 512; k += 32) {
        const float hv = __bfloat162float(hhi[k]) + __bfloat162float(hlo[k]);
        s = fmaf(hv, Wp[w * 512 + k], s);
    }
    #pragma unroll
    for (int o = 16; o > 0; o >>= 1)
        s += __shfl_xor_sync(0xffffffffu, s, o);
    if (lane == 0) out[w] = s + bp[w];
}

extern "C" void kernel_launch(void* const* d_in, const int* in_sizes, int n_in,
                              void* d_out, int out_size)
{
    const float* leaf  = (const float*)d_in[0];
    const float* Wemb  = (const float*)d_in[1];
    const float* bemb  = (const float*)d_in[2];
    const float* Wcomb = (const float*)d_in[3];
    const float* bcomb = (const float*)d_in[4];
    const float* Wproj = (const float*)d_in[5];
    const float* bproj = (const float*)d_in[6];
    float* out = (float*)d_out;

    __nv_bfloat16 *leaf_hi, *leaf_lo, *We_hi, *We_lo, *Wc_hi, *Wc_lo;
    __nv_bfloat16 *hA, *lA, *hB, *lB;
    cudaGetSymbolAddress((void**)&leaf_hi, g_leaf_hi);
    cudaGetSymbolAddress((void**)&leaf_lo, g_leaf_lo);
    cudaGetSymbolAddress((void**)&We_hi, g_We_hi);
    cudaGetSymbolAddress((void**)&We_lo, g_We_lo);
    cudaGetSymbolAddress((void**)&Wc_hi, g_Wc_hi);
    cudaGetSymbolAddress((void**)&Wc_lo, g_Wc_lo);
    cudaGetSymbolAddress((void**)&hA, g_hA);
    cudaGetSymbolAddress((void**)&lA, g_lA);
    cudaGetSymbolAddress((void**)&hB, g_hB);
    cudaGetSymbolAddress((void**)&lB, g_lB);

    cudaFuncSetAttribute(gemm64,
                         cudaFuncAttributeMaxDynamicSharedMemorySize, SMEM1);
    cudaFuncSetAttribute(tail_kernel,
                         cudaFuncAttributeMaxDynamicSharedMemorySize, SMEM3);

    // ---- pre-split fp32 inputs into bf16 hi/lo ----
    split_kernel<<<4096, 256>>>((const float4*)leaf,
                                (uint2*)leaf_hi, (uint2*)leaf_lo, 8192 * 4096 / 4);
    split_kernel<<<1024, 256>>>((const float4*)Wemb,
                                (uint2*)We_hi, (uint2*)We_lo, 512 * 4096 / 4);
    split_kernel<<<512, 256>>>((const float4*)Wcomb,
                               (uint2*)Wc_hi, (uint2*)Wc_lo, 512 * 1024 / 4);

    // ---- leaf embedding: [8192,4096] @ [512,4096]^T -> hA/lA ----
    {
        dim3 grid(512 / 64, 8192 / 128);
        gemm64<<<grid, 256, SMEM1>>>(leaf_hi, leaf_lo, We_hi, We_lo,
                                     bemb, hA, lA, 8192, 512, 4096);
    }

    // ---- mid combine levels m = 4096, 2048, 1024 ----
    __nv_bfloat16 *cur_h = hA, *cur_l = lA, *nxt_h = hB, *nxt_l = lB;
    int rows = 8192;
    while (rows > 1024) {
        const int m = rows / 2;
        dim3 grid(512 / 64, (m + 127) / 128);
        gemm64<<<grid, 256, SMEM1>>>(cur_h, cur_l, Wc_hi, Wc_lo,
                                     bcomb, nxt_h, nxt_l, m, 512, 1024);
        __nv_bfloat16* t;
        t = cur_h; cur_h = nxt_h; nxt_h = t;
        t = cur_l; cur_l = nxt_l; nxt_l = t;
        rows = m;
    }

    // ---- tail levels m = 512..1: one persistent kernel ----
    // 10 levels (even) -> final output lands back in (cur_h, cur_l).
    tail_kernel<<<NCTA_TAIL, 128, SMEM3>>>(cur_h, cur_l, nxt_h, nxt_l,
                                           Wc_hi, Wc_lo, bcomb);

    proj_kernel<<<1, 64>>>(cur_h, cur_l, Wproj, bproj, out);
}

// round 11
// speedup vs baseline: 1.0814x; 1.0814x over previous
#include <cuda_runtime.h>
#include <cuda_bf16.h>
#include <cuda_fp16.h>
#include <cstdint>

// Tree-RNN GEMMs on mma.sync tensor cores.
// Big GEMMs (leaf + m>=1024): fp16 2-term  C = A_h16 @ (W_hi + W_lo),
//   2 MMAs/tile, BK=64, 3-stage cp.async ring.
// Tail (m<=512): bf16x3 split-K(4) + finalize (R6-proven, latency-bound).

// ---------------- device scratch (no allocation allowed) ----------------
__device__ __half g_leaf16[8192ull * 4096];          // 64 MB
__device__ __half g_We_h[512 * 4096], g_We_l[512 * 4096];
__device__ __half g_Wc16_h[512 * 1024], g_Wc16_l[512 * 1024];
__device__ __nv_bfloat16 g_Wcb_h[512 * 1024], g_Wcb_l[512 * 1024];
__device__ __half g_P16[8192 * 512];                 // fp16 h ping (8 MB)
__device__ __half g_Q16[4096 * 512];                 // fp16 h pong (4 MB)
__device__ __nv_bfloat16 g_hB[1024 * 512], g_lB[1024 * 512];   // bf16 pair
__device__ __nv_bfloat16 g_hC[512 * 512],  g_lC[512 * 512];    // bf16 pair
#define KSPLIT 4
__device__ float g_part[KSPLIT * 512 * 512];         // split-K partials

// ---------------- PTX helpers ----------------
__device__ __forceinline__ void mma_bf16(float c[4], const uint32_t a[4],
                                         const uint32_t b0, const uint32_t b1) {
    asm volatile(
        "mma.sync.aligned.m16n8k16.row.col.f32.bf16.bf16.f32 "
        "{%0,%1,%2,%3}, {%4,%5,%6,%7}, {%8,%9}, {%0,%1,%2,%3};\n"
        : "+f"(c[0]), "+f"(c[1]), "+f"(c[2]), "+f"(c[3])
        : "r"(a[0]), "r"(a[1]), "r"(a[2]), "r"(a[3]), "r"(b0), "r"(b1));
}
__device__ __forceinline__ void mma_fp16(float c[4], const uint32_t a[4],
                                         const uint32_t b0, const uint32_t b1) {
    asm volatile(
        "mma.sync.aligned.m16n8k16.row.col.f32.f16.f16.f32 "
        "{%0,%1,%2,%3}, {%4,%5,%6,%7}, {%8,%9}, {%0,%1,%2,%3};\n"
        : "+f"(c[0]), "+f"(c[1]), "+f"(c[2]), "+f"(c[3])
        : "r"(a[0]), "r"(a[1]), "r"(a[2]), "r"(a[3]), "r"(b0), "r"(b1));
}
__device__ __forceinline__ void cp16(uint32_t dst, const void* src, bool p) {
    asm volatile("cp.async.cg.shared.global [%0], [%1], 16, %2;"
                 :: "r"(dst), "l"(src), "r"(p ? 16 : 0));
}
__device__ __forceinline__ void cp_commit() {
    asm volatile("cp.async.commit_group;");
}
template <int N> __device__ __forceinline__ void cp_wait() {
    asm volatile("cp.async.wait_group %0;" :: "n"(N));
}
__device__ __forceinline__ void ldsm4(uint32_t r[4], uint32_t a) {
    asm volatile("ldmatrix.sync.aligned.m8n8.x4.shared.b16 {%0,%1,%2,%3}, [%4];"
                 : "=r"(r[0]), "=r"(r[1]), "=r"(r[2]), "=r"(r[3]) : "r"(a));
}
__device__ __forceinline__ uint32_t pack_bf2(__nv_bfloat16 a, __nv_bfloat16 b) {
    __nv_bfloat162 t{a, b};
    return *reinterpret_cast<uint32_t*>(&t);
}
__device__ __forceinline__ uint32_t pack_h2(__half a, __half b) {
    __half2 t{a, b};
    return *reinterpret_cast<uint32_t*>(&t);
}

// ---------------- split kernels ----------------
__global__ void split_a_f16(const float4* __restrict__ src,
                            uint2* __restrict__ out, int n4)
{
    int i = blockIdx.x * blockDim.x + threadIdx.x;
    const int stride = gridDim.x * blockDim.x;
    for (; i < n4; i += stride) {
        float4 v = src[i];
        uint2 o;
        o.x = pack_h2(__float2half_rn(v.x), __float2half_rn(v.y));
        o.y = pack_h2(__float2half_rn(v.z), __float2half_rn(v.w));
        out[i] = o;
    }
}
__global__ void split_w_f16(const float4* __restrict__ src,
                            uint2* __restrict__ hi, uint2* __restrict__ lo,
                            int n4)
{
    int i = blockIdx.x * blockDim.x + threadIdx.x;
    const int stride = gridDim.x * blockDim.x;
    for (; i < n4; i += stride) {
        float4 v = src[i];
        __half h0 = __float2half_rn(v.x), h1 = __float2half_rn(v.y);
        __half h2 = __float2half_rn(v.z), h3 = __float2half_rn(v.w);
        uint2 H, L;
        H.x = pack_h2(h0, h1);
        H.y = pack_h2(h2, h3);
        L.x = pack_h2(__float2half_rn(v.x - __half2float(h0)),
                      __float2half_rn(v.y - __half2float(h1)));
        L.y = pack_h2(__float2half_rn(v.z - __half2float(h2)),
                      __float2half_rn(v.w - __half2float(h3)));
        hi[i] = H;
        lo[i] = L;
    }
}
__global__ void split_w_bf16(const float4* __restrict__ src,
                             uint2* __restrict__ hi, uint2* __restrict__ lo,
                             int n4)
{
    int i = blockIdx.x * blockDim.x + threadIdx.x;
    const int stride = gridDim.x * blockDim.x;
    for (; i < n4; i += stride) {
        float4 v = src[i];
        __nv_bfloat16 h0 = __float2bfloat16(v.x), h1 = __float2bfloat16(v.y);
        __nv_bfloat16 h2 = __float2bfloat16(v.z), h3 = __float2bfloat16(v.w);
        uint2 H, L;
        H.x = pack_bf2(h0, h1);
        H.y = pack_bf2(h2, h3);
        L.x = pack_bf2(__float2bfloat16(v.x - __bfloat162float(h0)),
                      __float2bfloat16(v.y - __bfloat162float(h1)));
        L.y = pack_bf2(__float2bfloat16(v.z - __bfloat162float(h2)),
                      __float2bfloat16(v.w - __bfloat162float(h3)));
        hi[i] = H;
        lo[i] = L;
    }
}

// ============================================================================
// gemm16<OUT>: C = relu(A @ (Wh+Wl)^T + bias), A fp16 single [M,K],
// W hi/lo fp16 [N,K]. OUT=0: C fp16 single. OUT=1: C bf16 hi/lo pair.
// Tile 128x64, BK=64, 3-stage ring, 8 warps (4M x 2N, warp 32x32).
// ============================================================================
#define A16_T 16384                 // A: 128 rows x 128B (64 fp16)
#define BH16_OFF 16384              // Bh: 64 x 128B
#define BL16_OFF 24576              // Bl: 64 x 128B
#define STAGE16 32768
#define SMEM16 (3 * STAGE16)        // 98304

template <int OUT>
__global__ __launch_bounds__(256, 2)
void gemm16(const __half* __restrict__ A,
            const __half* __restrict__ Whi,
            const __half* __restrict__ Wlo,
            const float* __restrict__ bias,
            __half* __restrict__ Cf16,
            __nv_bfloat16* __restrict__ Chi,
            __nv_bfloat16* __restrict__ Clo,
            int M, int N, int K)
{
    extern __shared__ __align__(1024) char smem[];
    const uint32_t sbase = (uint32_t)__cvta_generic_to_shared(smem);

    const int tid  = threadIdx.x;
    const int lane = tid & 31;
    const int wid  = tid >> 5;
    const int wm   = (wid & 3) * 32;
    const int wn   = (wid >> 2) * 32;
    const int bm   = blockIdx.y * 128;
    const int bn   = blockIdx.x * 64;

    const int lr8   = lane & 7;
    const int g     = lane >> 3;
    const int mrow  = (g & 1) * 8;
    const int kcolB = (g >> 1) * 16;

    uint32_t aRow[2], aXm[2], bRow[2], bXm[2];
    #pragma unroll
    for (int mi = 0; mi < 2; mi++) {
        const uint32_t rB = (uint32_t)(wm + mi * 16 + mrow + lr8) * 128;
        aRow[mi] = rB;
        aXm[mi]  = (rB >> 3) & 0x70;
    }
    #pragma unroll
    for (int p = 0; p < 2; p++) {
        const uint32_t rB = (uint32_t)(wn + p * 16 + mrow + lr8) * 128;
        bRow[p] = rB;
        bXm[p]  = (rB >> 3) & 0x70;
    }

    float acc[2][4][4];
    #pragma unroll
    for (int i = 0; i < 2; i++)
        #pragma unroll
        for (int j = 0; j < 4; j++)
            #pragma unroll
            for (int v = 0; v < 4; v++) acc[i][j][v] = 0.f;

    const int nT = K / 64;

    auto stage = [&](int lt) {
        const uint32_t sb = sbase + (uint32_t)(lt % 3) * STAGE16;
        const int k0 = lt * 64;
        // A: 128 rows x 8 chunks = 1024 chunks, 4/thread
        #pragma unroll
        for (int i = 0; i < 4; i++) {
            const int lin = tid + i * 256;
            const int r = lin >> 3;
            const int c = lin & 7;
            const uint32_t off = (uint32_t)r * 128 + (uint32_t)c * 16;
            const uint32_t sw = off ^ ((off >> 3) & 0x70);
            const bool pa = (bm + r) < M;
            cp16(sb + sw, A + (size_t)(bm + r) * K + k0 + c * 8, pa);
        }
        // B hi + lo: 64 rows x 8 chunks each = 512+512, 2+2/thread
        #pragma unroll
        for (int i = 0; i < 2; i++) {
            const int lin = tid + i * 256;
            const int r = lin >> 3;
            const int c = lin & 7;
            const uint32_t off = (uint32_t)r * 128 + (uint32_t)c * 16;
            const uint32_t sw = off ^ ((off >> 3) & 0x70);
            const size_t go = (size_t)(bn + r) * K + k0 + c * 8;
            cp16(sb + BH16_OFF + sw, Whi + go, true);
            cp16(sb + BL16_OFF + sw, Wlo + go, true);
        }
        cp_commit();
    };

    stage(0);
    stage(1);

    for (int kt = 0; kt < nT; kt++) {
        if (kt + 1 < nT) cp_wait<1>();
        else             cp_wait<0>();
        __syncthreads();
        if (kt + 2 < nT) stage(kt + 2);

        const uint32_t s0 = sbase + (uint32_t)(kt % 3) * STAGE16;

        #pragma unroll
        for (int ks = 0; ks < 64; ks += 16) {
            const uint32_t col = (uint32_t)(ks * 2) + kcolB;    // 0..112
            uint32_t ah[2][4], bh[2][4], bl[2][4];
            #pragma unroll
            for (int mi = 0; mi < 2; mi++)
                ldsm4(ah[mi], s0 + aRow[mi] + (col ^ aXm[mi]));
            #pragma unroll
            for (int p = 0; p < 2; p++) {
                ldsm4(bh[p], s0 + BH16_OFF + bRow[p] + (col ^ bXm[p]));
                ldsm4(bl[p], s0 + BL16_OFF + bRow[p] + (col ^ bXm[p]));
            }
            #pragma unroll
            for (int mi = 0; mi < 2; mi++)
                #pragma unroll
                for (int ni = 0; ni < 4; ni++) {
                    const int p = ni >> 1, q = ni & 1;
                    mma_fp16(acc[mi][ni], ah[mi], bh[p][q], bh[p][q + 2]);
                    mma_fp16(acc[mi][ni], ah[mi], bl[p][q], bl[p][q + 2]);
                }
        }
    }

    const int lq = (lane & 3) * 2;
    const int lr = lane >> 2;
    #pragma unroll
    for (int mi = 0; mi < 2; mi++) {
        #pragma unroll
        for (int ni = 0; ni < 4; ni++) {
            const int m0 = bm + wm + mi * 16 + lr;
            const int n  = bn + wn + ni * 8 + lq;
            const float bv0 = __ldg(bias + n), bv1 = __ldg(bias + n + 1);
            #pragma unroll
            for (int h = 0; h < 2; h++) {
                const int m = m0 + h * 8;
                if (m < M) {
                    float x0 = fmaxf(acc[mi][ni][2 * h]     + bv0, 0.f);
                    float x1 = fmaxf(acc[mi][ni][2 * h + 1] + bv1, 0.f);
                    if (OUT == 0) {
                        *reinterpret_cast<uint32_t*>(Cf16 + (size_t)m * N + n) =
                            pack_h2(__float2half_rn(x0), __float2half_rn(x1));
                    } else {
                        __nv_bfloat16 h0 = __float2bfloat16(x0);
                        __nv_bfloat16 h1 = __float2bfloat16(x1);
                        __nv_bfloat16 l0 = __float2bfloat16(x0 - __bfloat162float(h0));
                        __nv_bfloat16 l1 = __float2bfloat16(x1 - __bfloat162float(h1));
                        *reinterpret_cast<uint32_t*>(Chi + (size_t)m * N + n) = pack_bf2(h0, h1);
                        *reinterpret_cast<uint32_t*>(Clo + (size_t)m * N + n) = pack_bf2(l0, l1);
                    }
                }
            }
        }
    }
}

// ============================================================================
// gemm_small: bf16x3 split-K small-M GEMM (R6-proven). 32x64 tile,
// 128 threads, grid (N/64, ceil(M/32), KSPLIT). Writes fp32 partials.
// ============================================================================
#define A_T3 4096
#define STAGE3 12288
#define SMEM3 (3 * STAGE3)    // 36864

__global__ __launch_bounds__(128, 4)
void gemm_small(const __nv_bfloat16* __restrict__ Ahi,
                const __nv_bfloat16* __restrict__ Alo,
                const __nv_bfloat16* __restrict__ Whi,
                const __nv_bfloat16* __restrict__ Wlo,
                float* __restrict__ part,
                int M, int N, int K)
{
    extern __shared__ __align__(1024) char smem[];
    const uint32_t sbase = (uint32_t)__cvta_generic_to_shared(smem);

    const int tid  = threadIdx.x;
    const int lane = tid & 31;
    const int wid  = tid >> 5;
    const int wm   = (wid & 1) * 16;
    const int wn   = (wid >> 1) * 32;
    const int bm   = blockIdx.y * 32;
    const int bn   = blockIdx.x * 64;
    const int kbase = blockIdx.z * (K / KSPLIT);

    const int lr8   = lane & 7;
    const int g     = lane >> 3;
    const int mrow  = (g & 1) * 8;
    const int kcolB = (g >> 1) * 16;

    uint32_t aRowB, aXm, bRow[2], bXm[2];
    {
        const uint32_t rB = (uint32_t)(wm + mrow + lr8) * 128;
        aRowB = rB;
        aXm   = (rB >> 3) & 0x70;
    }
    #pragma unroll
    for (int p = 0; p < 2; p++) {
        const uint32_t rB = (uint32_t)(wn + p * 16 + mrow + lr8) * 128;
        bRow[p] = A_T3 + rB;
        bXm[p]  = (rB >> 3) & 0x70;
    }

    float acc[4][4];
    #pragma unroll
    for (int j = 0; j < 4; j++)
        #pragma unroll
        for (int v = 0; v < 4; v++) acc[j][v] = 0.f;

    const int nT = (K / KSPLIT) / 32;

    auto stage = [&](int lt) {
        const uint32_t sb = sbase + (uint32_t)(lt % 3) * STAGE3;
        const int k0 = kbase + lt * 32;
        #pragma unroll
        for (int i = 0; i < 2; i++) {
            const int lin = tid + i * 128;
            const int r = lin >> 3;
            const int c = lin & 7;
            const uint32_t off = (uint32_t)r * 128 + (uint32_t)c * 16;
            const uint32_t sw = off ^ ((off >> 3) & 0x70);
            const bool pa = (bm + r) < M;
            const __nv_bfloat16* src = (c < 4) ? Ahi : Alo;
            cp16(sb + sw, src + (size_t)(bm + r) * K + k0 + (c & 3) * 8, pa);
        }
        #pragma unroll
        for (int i = 0; i < 4; i++) {
            const int lin = tid + i * 128;
            const int r = lin >> 3;
            const int c = lin & 7;
            const uint32_t off = (uint32_t)r * 128 + (uint32_t)c * 16;
            const uint32_t sw = off ^ ((off >> 3) & 0x70);
            const __nv_bfloat16* src = (c < 4) ? Whi : Wlo;
            cp16(sb + A_T3 + sw, src + (size_t)(bn + r) * K + k0 + (c & 3) * 8, true);
        }
        cp_commit();
    };

    stage(0);
    stage(1);

    for (int kt = 0; kt < nT; kt++) {
        if (kt + 1 < nT) cp_wait<1>();
        else             cp_wait<0>();
        __syncthreads();
        if (kt + 2 < nT) stage(kt + 2);

        const uint32_t s0 = sbase + (uint32_t)(kt % 3) * STAGE3;

        #pragma unroll
        for (int ks = 0; ks < 32; ks += 16) {
            const uint32_t colH = (uint32_t)(ks * 2) + kcolB;
            const uint32_t colL = 64u + (uint32_t)(ks * 2) + kcolB;
            uint32_t ah[4], al[4], bh[2][4], bl[2][4];
            ldsm4(ah, s0 + aRowB + (colH ^ aXm));
            ldsm4(al, s0 + aRowB + (colL ^ aXm));
            #pragma unroll
            for (int p = 0; p < 2; p++) {
                ldsm4(bh[p], s0 + bRow[p] + (colH ^ bXm[p]));
                ldsm4(bl[p], s0 + bRow[p] + (colL ^ bXm[p]));
            }
            #pragma unroll
            for (int ni = 0; ni < 4; ni++) {
                const int p = ni >> 1, q = ni & 1;
                mma_bf16(acc[ni], ah, bh[p][q], bh[p][q + 2]);
                mma_bf16(acc[ni], ah, bl[p][q], bl[p][q + 2]);
                mma_bf16(acc[ni], al, bh[p][q], bh[p][q + 2]);
            }
        }
    }

    const int lq = (lane & 3) * 2;
    const int lr = lane >> 2;
    #pragma unroll
    for (int ni = 0; ni < 4; ni++) {
        const int m0 = bm + wm + lr;
        const int n  = bn + wn + ni * 8 + lq;
        #pragma unroll
        for (int h = 0; h < 2; h++) {
            const int m = m0 + h * 8;
            if (m < M) {
                float* dst = part + ((size_t)blockIdx.z * M + m) * N + n;
                dst[0] = acc[ni][2 * h];
                dst[1] = acc[ni][2 * h + 1];
            }
        }
    }
}

__global__ void finalize_small(const float* __restrict__ part,
                               const float* __restrict__ bias,
                               __nv_bfloat16* __restrict__ Chi,
                               __nv_bfloat16* __restrict__ Clo,
                               int M, int N)
{
    const int total2 = M * N / 2;
    int i = blockIdx.x * blockDim.x + threadIdx.x;
    const int stride = gridDim.x * blockDim.x;
    for (; i < total2; i += stride) {
        const int m = (2 * i) / N;
        const int n = (2 * i) % N;
        float s0 = 0.f, s1 = 0.f;
        #pragma unroll
        for (int z = 0; z < KSPLIT; z++) {
            const float* p = part + ((size_t)z * M + m) * N + n;
            s0 += p[0];
            s1 += p[1];
        }
        float x0 = fmaxf(s0 + bias[n], 0.f);
        float x1 = fmaxf(s1 + bias[n + 1], 0.f);
        __nv_bfloat16 h0 = __float2bfloat16(x0);
        __nv_bfloat16 h1 = __float2bfloat16(x1);
        __nv_bfloat16 l0 = __float2bfloat16(x0 - __bfloat162float(h0));
        __nv_bfloat16 l1 = __float2bfloat16(x1 - __bfloat162float(h1));
        *reinterpret_cast<uint32_t*>(Chi + (size_t)m * N + n) = pack_bf2(h0, h1);
        *reinterpret_cast<uint32_t*>(Clo + (size_t)m * N + n) = pack_bf2(l0, l1);
    }
}

// Root projection
__global__ void proj_kernel(const __nv_bfloat16* __restrict__ hhi,
                            const __nv_bfloat16* __restrict__ hlo,
                            const float* __restrict__ Wp,
                            const float* __restrict__ bp,
                            float* __restrict__ out)
{
    const int w    = threadIdx.x >> 5;
    const int lane = threadIdx.x & 31;
    float s = 0.f;
    for (int k = lane; k < 512; k += 32) {
        const float hv = __bfloat162float(hhi[k]) + __bfloat162float(hlo[k]);
        s = fmaf(hv, Wp[w * 512 + k], s);
    }
    #pragma unroll
    for (int o = 16; o > 0; o >>= 1)
        s += __shfl_xor_sync(0xffffffffu, s, o);
    if (lane == 0) out[w] = s + bp[w];
}

extern "C" void kernel_launch(void* const* d_in, const int* in_sizes, int n_in,
                              void* d_out, int out_size)
{
    const float* leaf  = (const float*)d_in[0];
    const float* Wemb  = (const float*)d_in[1];
    const float* bemb  = (const float*)d_in[2];
    const float* Wcomb = (const float*)d_in[3];
    const float* bcomb = (const float*)d_in[4];
    const float* Wproj = (const float*)d_in[5];
    const float* bproj = (const float*)d_in[6];
    float* out = (float*)d_out;

    __half *leaf16, *We_h, *We_l, *Wc16_h, *Wc16_l, *P16, *Q16;
    __nv_bfloat16 *Wcb_h, *Wcb_l, *hB, *lB, *hC, *lC;
    float* part;
    cudaGetSymbolAddress((void**)&leaf16, g_leaf16);
    cudaGetSymbolAddress((void**)&We_h, g_We_h);
    cudaGetSymbolAddress((void**)&We_l, g_We_l);
    cudaGetSymbolAddress((void**)&Wc16_h, g_Wc16_h);
    cudaGetSymbolAddress((void**)&Wc16_l, g_Wc16_l);
    cudaGetSymbolAddress((void**)&Wcb_h, g_Wcb_h);
    cudaGetSymbolAddress((void**)&Wcb_l, g_Wcb_l);
    cudaGetSymbolAddress((void**)&P16, g_P16);
    cudaGetSymbolAddress((void**)&Q16, g_Q16);
    cudaGetSymbolAddress((void**)&hB, g_hB);
    cudaGetSymbolAddress((void**)&lB, g_lB);
    cudaGetSymbolAddress((void**)&hC, g_hC);
    cudaGetSymbolAddress((void**)&lC, g_lC);
    cudaGetSymbolAddress((void**)&part, g_part);

    cudaFuncSetAttribute(gemm16<0>,
                         cudaFuncAttributeMaxDynamicSharedMemorySize, SMEM16);
    cudaFuncSetAttribute(gemm16<1>,
                         cudaFuncAttributeMaxDynamicSharedMemorySize, SMEM16);
    cudaFuncSetAttribute(gemm_small,
                         cudaFuncAttributeMaxDynamicSharedMemorySize, SMEM3);

    // ---- convert/split inputs ----
    split_a_f16<<<4096, 256>>>((const float4*)leaf, (uint2*)leaf16,
                               8192 * 4096 / 4);
    split_w_f16<<<512, 256>>>((const float4*)Wemb, (uint2*)We_h, (uint2*)We_l,
                              512 * 4096 / 4);
    split_w_f16<<<128, 256>>>((const float4*)Wcomb, (uint2*)Wc16_h, (uint2*)Wc16_l,
                              512 * 1024 / 4);
    split_w_bf16<<<128, 256>>>((const float4*)Wcomb, (uint2*)Wcb_h, (uint2*)Wcb_l,
                               512 * 1024 / 4);

    // ---- leaf: [8192,4096] @ [512,4096]^T -> P16 (fp16) ----
    {
        dim3 grid(512 / 64, 8192 / 128);
        gemm16<0><<<grid, 256, SMEM16>>>(leaf16, We_h, We_l, bemb,
                                         P16, nullptr, nullptr, 8192, 512, 4096);
    }
    // ---- m = 4096: P16 -> Q16 ----
    {
        dim3 grid(512 / 64, 4096 / 128);
        gemm16<0><<<grid, 256, SMEM16>>>(P16, Wc16_h, Wc16_l, bcomb,
                                         Q16, nullptr, nullptr, 4096, 512, 1024);
    }
    // ---- m = 2048: Q16 -> P16 ----
    {
        dim3 grid(512 / 64, 2048 / 128);
        gemm16<0><<<grid, 256, SMEM16>>>(Q16, Wc16_h, Wc16_l, bcomb,
                                         P16, nullptr, nullptr, 2048, 512, 1024);
    }
    // ---- m = 1024: P16 -> (hB, lB) bf16 pair ----
    {
        dim3 grid(512 / 64, 1024 / 128);
        gemm16<1><<<grid, 256, SMEM16>>>(P16, Wc16_h, Wc16_l, bcomb,
                                         nullptr, hB, lB, 1024, 512, 1024);
    }

    // ---- tail m = 512..1: bf16x3 split-K + finalize ----
    __nv_bfloat16 *cur_h = hB, *cur_l = lB, *nxt_h = hC, *nxt_l = lC;
    for (int m = 512; m >= 1; m >>= 1) {
        dim3 grid(512 / 64, (m + 31) / 32, KSPLIT);
        gemm_small<<<grid, 128, SMEM3>>>(cur_h, cur_l, Wcb_h, Wcb_l,
                                         part, m, 512, 1024);
        const int total2 = m * 512 / 2;
        const int blocks = (total2 + 255) / 256;
        finalize_small<<<blocks, 256>>>(part, bcomb, nxt_h, nxt_l, m, 512);
        __nv_bfloat16* t;
        t = cur_h; cur_h = nxt_h; nxt_h = t;
        t = cur_l; cur_l = nxt_l; nxt_l = t;
    }

    proj_kernel<<<1, 64>>>(cur_h, cur_l, Wproj, bproj, out);
}

// round 12
// speedup vs baseline: 1.5327x; 1.4174x over previous
#include <cuda_runtime.h>
#include <cuda_bf16.h>
#include <cuda_fp16.h>
#include <cstdint>

// Tree-RNN GEMMs on mma.sync tensor cores.
// Big GEMMs (leaf + m>=1024): fp16 2-term  C = A_h16 @ (W_hi + W_lo).
// Tail (m<=512): bf16x3 split-K(4) with FUSED finalize (ticket counter).

// ---------------- device scratch (no allocation allowed) ----------------
__device__ __half g_leaf16[8192ull * 4096];          // 64 MB
__device__ __half g_We_h[512 * 4096], g_We_l[512 * 4096];
__device__ __half g_Wc16_h[512 * 1024], g_Wc16_l[512 * 1024];
__device__ __nv_bfloat16 g_Wcb_h[512 * 1024], g_Wcb_l[512 * 1024];
__device__ __half g_P16[8192 * 512];                 // fp16 ping
__device__ __half g_Q16[4096 * 512];                 // fp16 pong
__device__ __nv_bfloat16 g_hB[1024 * 512], g_lB[1024 * 512];
__device__ __nv_bfloat16 g_hC[512 * 512],  g_lC[512 * 512];
#define KSPLIT 4
__device__ float g_part[KSPLIT * 512 * 512];
__device__ unsigned g_ticket[128];                   // zero-init, self-reset

// ---------------- PTX helpers ----------------
__device__ __forceinline__ void mma_bf16(float c[4], const uint32_t a[4],
                                         const uint32_t b0, const uint32_t b1) {
    asm volatile(
        "mma.sync.aligned.m16n8k16.row.col.f32.bf16.bf16.f32 "
        "{%0,%1,%2,%3}, {%4,%5,%6,%7}, {%8,%9}, {%0,%1,%2,%3};\n"
        : "+f"(c[0]), "+f"(c[1]), "+f"(c[2]), "+f"(c[3])
        : "r"(a[0]), "r"(a[1]), "r"(a[2]), "r"(a[3]), "r"(b0), "r"(b1));
}
__device__ __forceinline__ void mma_fp16(float c[4], const uint32_t a[4],
                                         const uint32_t b0, const uint32_t b1) {
    asm volatile(
        "mma.sync.aligned.m16n8k16.row.col.f32.f16.f16.f32 "
        "{%0,%1,%2,%3}, {%4,%5,%6,%7}, {%8,%9}, {%0,%1,%2,%3};\n"
        : "+f"(c[0]), "+f"(c[1]), "+f"(c[2]), "+f"(c[3])
        : "r"(a[0]), "r"(a[1]), "r"(a[2]), "r"(a[3]), "r"(b0), "r"(b1));
}
__device__ __forceinline__ void cp16(uint32_t dst, const void* src, bool p) {
    asm volatile("cp.async.cg.shared.global [%0], [%1], 16, %2;"
                 :: "r"(dst), "l"(src), "r"(p ? 16 : 0));
}
__device__ __forceinline__ void cp_commit() {
    asm volatile("cp.async.commit_group;");
}
template <int N> __device__ __forceinline__ void cp_wait() {
    asm volatile("cp.async.wait_group %0;" :: "n"(N));
}
__device__ __forceinline__ void ldsm4(uint32_t r[4], uint32_t a) {
    asm volatile("ldmatrix.sync.aligned.m8n8.x4.shared.b16 {%0,%1,%2,%3}, [%4];"
                 : "=r"(r[0]), "=r"(r[1]), "=r"(r[2]), "=r"(r[3]) : "r"(a));
}
__device__ __forceinline__ uint32_t pack_bf2(__nv_bfloat16 a, __nv_bfloat16 b) {
    __nv_bfloat162 t{a, b};
    return *reinterpret_cast<uint32_t*>(&t);
}
__device__ __forceinline__ uint32_t pack_h2(__half a, __half b) {
    __half2 t{a, b};
    return *reinterpret_cast<uint32_t*>(&t);
}

// ---------------- split kernels ----------------
__global__ void split_a_f16(const float4* __restrict__ src,
                            uint2* __restrict__ out, int n4)
{
    int i = blockIdx.x * blockDim.x + threadIdx.x;
    const int stride = gridDim.x * blockDim.x;
    for (; i < n4; i += stride) {
        float4 v = src[i];
        uint2 o;
        o.x = pack_h2(__float2half_rn(v.x), __float2half_rn(v.y));
        o.y = pack_h2(__float2half_rn(v.z), __float2half_rn(v.w));
        out[i] = o;
    }
}
__global__ void split_w_f16(const float4* __restrict__ src,
                            uint2* __restrict__ hi, uint2* __restrict__ lo,
                            int n4)
{
    int i = blockIdx.x * blockDim.x + threadIdx.x;
    const int stride = gridDim.x * blockDim.x;
    for (; i < n4; i += stride) {
        float4 v = src[i];
        __half h0 = __float2half_rn(v.x), h1 = __float2half_rn(v.y);
        __half h2 = __float2half_rn(v.z), h3 = __float2half_rn(v.w);
        uint2 H, L;
        H.x = pack_h2(h0, h1);
        H.y = pack_h2(h2, h3);
        L.x = pack_h2(__float2half_rn(v.x - __half2float(h0)),
                      __float2half_rn(v.y - __half2float(h1)));
        L.y = pack_h2(__float2half_rn(v.z - __half2float(h2)),
                      __float2half_rn(v.w - __half2float(h3)));
        hi[i] = H;
        lo[i] = L;
    }
}
// one pass over Wcomb producing fp16 hi/lo AND bf16 hi/lo
__global__ void split_wc(const float4* __restrict__ src,
                         uint2* __restrict__ h16, uint2* __restrict__ l16,
                         uint2* __restrict__ hbf, uint2* __restrict__ lbf,
                         int n4)
{
    int i = blockIdx.x * blockDim.x + threadIdx.x;
    const int stride = gridDim.x * blockDim.x;
    for (; i < n4; i += stride) {
        float4 v = src[i];
        // fp16 pair
        __half f0 = __float2half_rn(v.x), f1 = __float2half_rn(v.y);
        __half f2 = __float2half_rn(v.z), f3 = __float2half_rn(v.w);
        uint2 FH, FL;
        FH.x = pack_h2(f0, f1);
        FH.y = pack_h2(f2, f3);
        FL.x = pack_h2(__float2half_rn(v.x - __half2float(f0)),
                       __float2half_rn(v.y - __half2float(f1)));
        FL.y = pack_h2(__float2half_rn(v.z - __half2float(f2)),
                       __float2half_rn(v.w - __half2float(f3)));
        h16[i] = FH;
        l16[i] = FL;
        // bf16 pair
        __nv_bfloat16 b0 = __float2bfloat16(v.x), b1 = __float2bfloat16(v.y);
        __nv_bfloat16 b2 = __float2bfloat16(v.z), b3 = __float2bfloat16(v.w);
        uint2 BH, BL;
        BH.x = pack_bf2(b0, b1);
        BH.y = pack_bf2(b2, b3);
        BL.x = pack_bf2(__float2bfloat16(v.x - __bfloat162float(b0)),
                        __float2bfloat16(v.y - __bfloat162float(b1)));
        BL.y = pack_bf2(__float2bfloat16(v.z - __bfloat162float(b2)),
                        __float2bfloat16(v.w - __bfloat162float(b3)));
        hbf[i] = BH;
        lbf[i] = BL;
    }
}

// ============================================================================
// gemm16<OUT>: C = relu(A @ (Wh+Wl)^T + bias). A fp16 [M,K], W hi/lo fp16.
// OUT=0: C fp16. OUT=1: C bf16 hi/lo pair. (R11-proven.)
// ============================================================================
#define BH16_OFF 16384
#define BL16_OFF 24576
#define STAGE16 32768
#define SMEM16 (3 * STAGE16)

template <int OUT>
__global__ __launch_bounds__(256, 2)
void gemm16(const __half* __restrict__ A,
            const __half* __restrict__ Whi,
            const __half* __restrict__ Wlo,
            const float* __restrict__ bias,
            __half* __restrict__ Cf16,
            __nv_bfloat16* __restrict__ Chi,
            __nv_bfloat16* __restrict__ Clo,
            int M, int N, int K)
{
    extern __shared__ __align__(1024) char smem[];
    const uint32_t sbase = (uint32_t)__cvta_generic_to_shared(smem);

    const int tid  = threadIdx.x;
    const int lane = tid & 31;
    const int wid  = tid >> 5;
    const int wm   = (wid & 3) * 32;
    const int wn   = (wid >> 2) * 32;
    const int bm   = blockIdx.y * 128;
    const int bn   = blockIdx.x * 64;

    const int lr8   = lane & 7;
    const int g     = lane >> 3;
    const int mrow  = (g & 1) * 8;
    const int kcolB = (g >> 1) * 16;

    uint32_t aRow[2], aXm[2], bRow[2], bXm[2];
    #pragma unroll
    for (int mi = 0; mi < 2; mi++) {
        const uint32_t rB = (uint32_t)(wm + mi * 16 + mrow + lr8) * 128;
        aRow[mi] = rB;
        aXm[mi]  = (rB >> 3) & 0x70;
    }
    #pragma unroll
    for (int p = 0; p < 2; p++) {
        const uint32_t rB = (uint32_t)(wn + p * 16 + mrow + lr8) * 128;
        bRow[p] = rB;
        bXm[p]  = (rB >> 3) & 0x70;
    }

    float acc[2][4][4];
    #pragma unroll
    for (int i = 0; i < 2; i++)
        #pragma unroll
        for (int j = 0; j < 4; j++)
            #pragma unroll
            for (int v = 0; v < 4; v++) acc[i][j][v] = 0.f;

    const int nT = K / 64;

    auto stage = [&](int lt) {
        const uint32_t sb = sbase + (uint32_t)(lt % 3) * STAGE16;
        const int k0 = lt * 64;
        #pragma unroll
        for (int i = 0; i < 4; i++) {
            const int lin = tid + i * 256;
            const int r = lin >> 3;
            const int c = lin & 7;
            const uint32_t off = (uint32_t)r * 128 + (uint32_t)c * 16;
            const uint32_t sw = off ^ ((off >> 3) & 0x70);
            const bool pa = (bm + r) < M;
            cp16(sb + sw, A + (size_t)(bm + r) * K + k0 + c * 8, pa);
        }
        #pragma unroll
        for (int i = 0; i < 2; i++) {
            const int lin = tid + i * 256;
            const int r = lin >> 3;
            const int c = lin & 7;
            const uint32_t off = (uint32_t)r * 128 + (uint32_t)c * 16;
            const uint32_t sw = off ^ ((off >> 3) & 0x70);
            const size_t go = (size_t)(bn + r) * K + k0 + c * 8;
            cp16(sb + BH16_OFF + sw, Whi + go, true);
            cp16(sb + BL16_OFF + sw, Wlo + go, true);
        }
        cp_commit();
    };

    stage(0);
    stage(1);

    for (int kt = 0; kt < nT; kt++) {
        if (kt + 1 < nT) cp_wait<1>();
        else             cp_wait<0>();
        __syncthreads();
        if (kt + 2 < nT) stage(kt + 2);

        const uint32_t s0 = sbase + (uint32_t)(kt % 3) * STAGE16;

        #pragma unroll
        for (int ks = 0; ks < 64; ks += 16) {
            const uint32_t col = (uint32_t)(ks * 2) + kcolB;
            uint32_t ah[2][4], bh[2][4], bl[2][4];
            #pragma unroll
            for (int mi = 0; mi < 2; mi++)
                ldsm4(ah[mi], s0 + aRow[mi] + (col ^ aXm[mi]));
            #pragma unroll
            for (int p = 0; p < 2; p++) {
                ldsm4(bh[p], s0 + BH16_OFF + bRow[p] + (col ^ bXm[p]));
                ldsm4(bl[p], s0 + BL16_OFF + bRow[p] + (col ^ bXm[p]));
            }
            #pragma unroll
            for (int mi = 0; mi < 2; mi++)
                #pragma unroll
                for (int ni = 0; ni < 4; ni++) {
                    const int p = ni >> 1, q = ni & 1;
                    mma_fp16(acc[mi][ni], ah[mi], bh[p][q], bh[p][q + 2]);
                    mma_fp16(acc[mi][ni], ah[mi], bl[p][q], bl[p][q + 2]);
                }
        }
    }

    const int lq = (lane & 3) * 2;
    const int lr = lane >> 2;
    #pragma unroll
    for (int mi = 0; mi < 2; mi++) {
        #pragma unroll
        for (int ni = 0; ni < 4; ni++) {
            const int m0 = bm + wm + mi * 16 + lr;
            const int n  = bn + wn + ni * 8 + lq;
            const float bv0 = __ldg(bias + n), bv1 = __ldg(bias + n + 1);
            #pragma unroll
            for (int h = 0; h < 2; h++) {
                const int m = m0 + h * 8;
                if (m < M) {
                    float x0 = fmaxf(acc[mi][ni][2 * h]     + bv0, 0.f);
                    float x1 = fmaxf(acc[mi][ni][2 * h + 1] + bv1, 0.f);
                    if (OUT == 0) {
                        *reinterpret_cast<uint32_t*>(Cf16 + (size_t)m * N + n) =
                            pack_h2(__float2half_rn(x0), __float2half_rn(x1));
                    } else {
                        __nv_bfloat16 h0 = __float2bfloat16(x0);
                        __nv_bfloat16 h1 = __float2bfloat16(x1);
                        __nv_bfloat16 l0 = __float2bfloat16(x0 - __bfloat162float(h0));
                        __nv_bfloat16 l1 = __float2bfloat16(x1 - __bfloat162float(h1));
                        *reinterpret_cast<uint32_t*>(Chi + (size_t)m * N + n) = pack_bf2(h0, h1);
                        *reinterpret_cast<uint32_t*>(Clo + (size_t)m * N + n) = pack_bf2(l0, l1);
                    }
                }
            }
        }
    }
}

// ============================================================================
// gemm_small_fused: bf16x3 split-K(4) with fused finalize. 32x64 tile,
// 128 threads, grid (N/64, ceil(M/32), KSPLIT). The LAST-arriving z-CTA
// per tile (ticket counter, self-resetting) sums the 4 partials in fixed
// z order, applies bias+relu, writes hi/lo bf16.
// ============================================================================
#define A_T3 4096
#define STAGE3 12288
#define SMEM3 (3 * STAGE3)

__global__ __launch_bounds__(128, 4)
void gemm_small_fused(const __nv_bfloat16* __restrict__ Ahi,
                      const __nv_bfloat16* __restrict__ Alo,
                      const __nv_bfloat16* __restrict__ Whi,
                      const __nv_bfloat16* __restrict__ Wlo,
                      const float* __restrict__ bias,
                      float* __restrict__ part,
                      unsigned* __restrict__ ticket,
                      __nv_bfloat16* __restrict__ Chi,
                      __nv_bfloat16* __restrict__ Clo,
                      int M, int N, int K)
{
    extern __shared__ __align__(1024) char smem[];
    const uint32_t sbase = (uint32_t)__cvta_generic_to_shared(smem);

    const int tid  = threadIdx.x;
    const int lane = tid & 31;
    const int wid  = tid >> 5;
    const int wm   = (wid & 1) * 16;
    const int wn   = (wid >> 1) * 32;
    const int bm   = blockIdx.y * 32;
    const int bn   = blockIdx.x * 64;
    const int kbase = blockIdx.z * (K / KSPLIT);

    const int lr8   = lane & 7;
    const int g     = lane >> 3;
    const int mrow  = (g & 1) * 8;
    const int kcolB = (g >> 1) * 16;

    uint32_t aRowB, aXm, bRow[2], bXm[2];
    {
        const uint32_t rB = (uint32_t)(wm + mrow + lr8) * 128;
        aRowB = rB;
        aXm   = (rB >> 3) & 0x70;
    }
    #pragma unroll
    for (int p = 0; p < 2; p++) {
        const uint32_t rB = (uint32_t)(wn + p * 16 + mrow + lr8) * 128;
        bRow[p] = A_T3 + rB;
        bXm[p]  = (rB >> 3) & 0x70;
    }

    float acc[4][4];
    #pragma unroll
    for (int j = 0; j < 4; j++)
        #pragma unroll
        for (int v = 0; v < 4; v++) acc[j][v] = 0.f;

    const int nT = (K / KSPLIT) / 32;

    auto stage = [&](int lt) {
        const uint32_t sb = sbase + (uint32_t)(lt % 3) * STAGE3;
        const int k0 = kbase + lt * 32;
        #pragma unroll
        for (int i = 0; i < 2; i++) {
            const int lin = tid + i * 128;
            const int r = lin >> 3;
            const int c = lin & 7;
            const uint32_t off = (uint32_t)r * 128 + (uint32_t)c * 16;
            const uint32_t sw = off ^ ((off >> 3) & 0x70);
            const bool pa = (bm + r) < M;
            const __nv_bfloat16* src = (c < 4) ? Ahi : Alo;
            cp16(sb + sw, src + (size_t)(bm + r) * K + k0 + (c & 3) * 8, pa);
        }
        #pragma unroll
        for (int i = 0; i < 4; i++) {
            const int lin = tid + i * 128;
            const int r = lin >> 3;
            const int c = lin & 7;
            const uint32_t off = (uint32_t)r * 128 + (uint32_t)c * 16;
            const uint32_t sw = off ^ ((off >> 3) & 0x70);
            const __nv_bfloat16* src = (c < 4) ? Whi : Wlo;
            cp16(sb + A_T3 + sw, src + (size_t)(bn + r) * K + k0 + (c & 3) * 8, true);
        }
        cp_commit();
    };

    stage(0);
    stage(1);

    for (int kt = 0; kt < nT; kt++) {
        if (kt + 1 < nT) cp_wait<1>();
        else             cp_wait<0>();
        __syncthreads();
        if (kt + 2 < nT) stage(kt + 2);

        const uint32_t s0 = sbase + (uint32_t)(kt % 3) * STAGE3;

        #pragma unroll
        for (int ks = 0; ks < 32; ks += 16) {
            const uint32_t colH = (uint32_t)(ks * 2) + kcolB;
            const uint32_t colL = 64u + (uint32_t)(ks * 2) + kcolB;
            uint32_t ah[4], al[4], bh[2][4], bl[2][4];
            ldsm4(ah, s0 + aRowB + (colH ^ aXm));
            ldsm4(al, s0 + aRowB + (colL ^ aXm));
            #pragma unroll
            for (int p = 0; p < 2; p++) {
                ldsm4(bh[p], s0 + bRow[p] + (colH ^ bXm[p]));
                ldsm4(bl[p], s0 + bRow[p] + (colL ^ bXm[p]));
            }
            #pragma unroll
            for (int ni = 0; ni < 4; ni++) {
                const int p = ni >> 1, q = ni & 1;
                mma_bf16(acc[ni], ah, bh[p][q], bh[p][q + 2]);
                mma_bf16(acc[ni], ah, bl[p][q], bl[p][q + 2]);
                mma_bf16(acc[ni], al, bh[p][q], bh[p][q + 2]);
            }
        }
    }

    // write fp32 partials
    const int lq = (lane & 3) * 2;
    const int lr = lane >> 2;
    #pragma unroll
    for (int ni = 0; ni < 4; ni++) {
        const int m0 = bm + wm + lr;
        const int n  = bn + wn + ni * 8 + lq;
        #pragma unroll
        for (int h = 0; h < 2; h++) {
            const int m = m0 + h * 8;
            if (m < M) {
                float* dst = part + ((size_t)blockIdx.z * M + m) * N + n;
                dst[0] = acc[ni][2 * h];
                dst[1] = acc[ni][2 * h + 1];
            }
        }
    }

    // ---- ticket: last z-CTA of this tile finalizes ----
    __threadfence();
    __syncthreads();
    __shared__ unsigned s_old;
    const int tileId = (int)blockIdx.y * (int)gridDim.x + (int)blockIdx.x;
    if (tid == 0) s_old = atomicAdd(&ticket[tileId], 1u);
    __syncthreads();
    if (s_old == KSPLIT - 1) {
        __threadfence();   // acquire: other CTAs' partials now visible
        // 32x64 tile = 2048 outputs; 128 threads x 16 (8 float2 pairs)
        for (int idx = tid * 2; idx < 32 * 64; idx += 256) {
            const int lm = idx >> 6;
            const int ln = idx & 63;
            const int m = bm + lm;
            if (m >= M) break;
            const int n = bn + ln;
            float s0 = 0.f, s1 = 0.f;
            #pragma unroll
            for (int z = 0; z < KSPLIT; z++) {
                const float* p = part + ((size_t)z * M + m) * N + n;
                s0 += p[0];
                s1 += p[1];
            }
            float x0 = fmaxf(s0 + __ldg(bias + n), 0.f);
            float x1 = fmaxf(s1 + __ldg(bias + n + 1), 0.f);
            __nv_bfloat16 h0 = __float2bfloat16(x0);
            __nv_bfloat16 h1 = __float2bfloat16(x1);
            __nv_bfloat16 l0 = __float2bfloat16(x0 - __bfloat162float(h0));
            __nv_bfloat16 l1 = __float2bfloat16(x1 - __bfloat162float(h1));
            *reinterpret_cast<uint32_t*>(Chi + (size_t)m * N + n) = pack_bf2(h0, h1);
            *reinterpret_cast<uint32_t*>(Clo + (size_t)m * N + n) = pack_bf2(l0, l1);
        }
        if (tid == 0) ticket[tileId] = 0;   // self-reset for next replay/level
    }
}

// Root projection
__global__ void proj_kernel(const __nv_bfloat16* __restrict__ hhi,
                            const __nv_bfloat16* __restrict__ hlo,
                            const float* __restrict__ Wp,
                            const float* __restrict__ bp,
                            float* __restrict__ out)
{
    const int w    = threadIdx.x >> 5;
    const int lane = threadIdx.x & 31;
    float s = 0.f;
    for (int k = lane; k < 512; k += 32) {
        const float hv = __bfloat162float(hhi[k]) + __bfloat162float(hlo[k]);
        s = fmaf(hv, Wp[w * 512 + k], s);
    }
    #pragma unroll
    for (int o = 16; o > 0; o >>= 1)
        s += __shfl_xor_sync(0xffffffffu, s, o);
    if (lane == 0) out[w] = s + bp[w];
}

extern "C" void kernel_launch(void* const* d_in, const int* in_sizes, int n_in,
                              void* d_out, int out_size)
{
    const float* leaf  = (const float*)d_in[0];
    const float* Wemb  = (const float*)d_in[1];
    const float* bemb  = (const float*)d_in[2];
    const float* Wcomb = (const float*)d_in[3];
    const float* bcomb = (const float*)d_in[4];
    const float* Wproj = (const float*)d_in[5];
    const float* bproj = (const float*)d_in[6];
    float* out = (float*)d_out;

    __half *leaf16, *We_h, *We_l, *Wc16_h, *Wc16_l, *P16, *Q16;
    __nv_bfloat16 *Wcb_h, *Wcb_l, *hB, *lB, *hC, *lC;
    float* part;
    unsigned* ticket;
    cudaGetSymbolAddress((void**)&leaf16, g_leaf16);
    cudaGetSymbolAddress((void**)&We_h, g_We_h);
    cudaGetSymbolAddress((void**)&We_l, g_We_l);
    cudaGetSymbolAddress((void**)&Wc16_h, g_Wc16_h);
    cudaGetSymbolAddress((void**)&Wc16_l, g_Wc16_l);
    cudaGetSymbolAddress((void**)&Wcb_h, g_Wcb_h);
    cudaGetSymbolAddress((void**)&Wcb_l, g_Wcb_l);
    cudaGetSymbolAddress((void**)&P16, g_P16);
    cudaGetSymbolAddress((void**)&Q16, g_Q16);
    cudaGetSymbolAddress((void**)&hB, g_hB);
    cudaGetSymbolAddress((void**)&lB, g_lB);
    cudaGetSymbolAddress((void**)&hC, g_hC);
    cudaGetSymbolAddress((void**)&lC, g_lC);
    cudaGetSymbolAddress((void**)&part, g_part);
    cudaGetSymbolAddress((void**)&ticket, g_ticket);

    cudaFuncSetAttribute(gemm16<0>,
                         cudaFuncAttributeMaxDynamicSharedMemorySize, SMEM16);
    cudaFuncSetAttribute(gemm16<1>,
                         cudaFuncAttributeMaxDynamicSharedMemorySize, SMEM16);
    cudaFuncSetAttribute(gemm_small_fused,
                         cudaFuncAttributeMaxDynamicSharedMemorySize, SMEM3);

    // ---- convert/split inputs (3 launches) ----
    split_a_f16<<<4096, 256>>>((const float4*)leaf, (uint2*)leaf16,
                               8192 * 4096 / 4);
    split_w_f16<<<512, 256>>>((const float4*)Wemb, (uint2*)We_h, (uint2*)We_l,
                              512 * 4096 / 4);
    split_wc<<<128, 256>>>((const float4*)Wcomb,
                           (uint2*)Wc16_h, (uint2*)Wc16_l,
                           (uint2*)Wcb_h, (uint2*)Wcb_l, 512 * 1024 / 4);

    // ---- leaf: -> P16 ----
    {
        dim3 grid(512 / 64, 8192 / 128);
        gemm16<0><<<grid, 256, SMEM16>>>(leaf16, We_h, We_l, bemb,
                                         P16, nullptr, nullptr, 8192, 512, 4096);
    }
    // ---- m = 4096 -> Q16, m = 2048 -> P16, m = 1024 -> bf16 pair ----
    {
        dim3 grid(512 / 64, 4096 / 128);
        gemm16<0><<<grid, 256, SMEM16>>>(P16, Wc16_h, Wc16_l, bcomb,
                                         Q16, nullptr, nullptr, 4096, 512, 1024);
    }
    {
        dim3 grid(512 / 64, 2048 / 128);
        gemm16<0><<<grid, 256, SMEM16>>>(Q16, Wc16_h, Wc16_l, bcomb,
                                         P16, nullptr, nullptr, 2048, 512, 1024);
    }
    {
        dim3 grid(512 / 64, 1024 / 128);
        gemm16<1><<<grid, 256, SMEM16>>>(P16, Wc16_h, Wc16_l, bcomb,
                                         nullptr, hB, lB, 1024, 512, 1024);
    }

    // ---- tail m = 512..1: split-K with fused finalize (10 launches) ----
    __nv_bfloat16 *cur_h = hB, *cur_l = lB, *nxt_h = hC, *nxt_l = lC;
    for (int m = 512; m >= 1; m >>= 1) {
        dim3 grid(512 / 64, (m + 31) / 32, KSPLIT);
        gemm_small_fused<<<grid, 128, SMEM3>>>(cur_h, cur_l, Wcb_h, Wcb_l,
                                               bcomb, part, ticket,
                                               nxt_h, nxt_l, m, 512, 1024);
        __nv_bfloat16* t;
        t = cur_h; cur_h = nxt_h; nxt_h = t;
        t = cur_l; cur_l = nxt_l; nxt_l = t;
    }

    proj_kernel<<<1, 64>>>(cur_h, cur_l, Wproj, bproj, out);
}

// round 13
// speedup vs baseline: 2.0929x; 1.3655x over previous
#include <cuda_runtime.h>
#include <cuda_bf16.h>
#include <cuda_fp16.h>
#include <cstdint>

// Tree-RNN GEMMs on mma.sync tensor cores.
// Leaf + mids (m>=1024): PURE fp16 GEMM (single term, 1 MMA/tile-step),
//   128x64 tile, BK=64, 4-stage cp.async ring, prefetch distance 3.
// Tail (m<=512): bf16x3 split-K(4) with fused finalize (R12-proven).

// ---------------- device scratch (no allocation allowed) ----------------
__device__ __half g_leaf16[8192ull * 4096];          // 64 MB
__device__ __half g_We16[512 * 4096];
__device__ __half g_Wc16[512 * 1024];
__device__ __nv_bfloat16 g_Wcb_h[512 * 1024], g_Wcb_l[512 * 1024];
__device__ __half g_P16[8192 * 512];                 // fp16 ping
__device__ __half g_Q16[4096 * 512];                 // fp16 pong
__device__ __nv_bfloat16 g_hB[1024 * 512], g_lB[1024 * 512];
__device__ __nv_bfloat16 g_hC[512 * 512],  g_lC[512 * 512];
#define KSPLIT 4
__device__ float g_part[KSPLIT * 512 * 512];
__device__ unsigned g_ticket[128];                   // zero-init, self-reset

// ---------------- PTX helpers ----------------
__device__ __forceinline__ void mma_bf16(float c[4], const uint32_t a[4],
                                         const uint32_t b0, const uint32_t b1) {
    asm volatile(
        "mma.sync.aligned.m16n8k16.row.col.f32.bf16.bf16.f32 "
        "{%0,%1,%2,%3}, {%4,%5,%6,%7}, {%8,%9}, {%0,%1,%2,%3};\n"
        : "+f"(c[0]), "+f"(c[1]), "+f"(c[2]), "+f"(c[3])
        : "r"(a[0]), "r"(a[1]), "r"(a[2]), "r"(a[3]), "r"(b0), "r"(b1));
}
__device__ __forceinline__ void mma_fp16(float c[4], const uint32_t a[4],
                                         const uint32_t b0, const uint32_t b1) {
    asm volatile(
        "mma.sync.aligned.m16n8k16.row.col.f32.f16.f16.f32 "
        "{%0,%1,%2,%3}, {%4,%5,%6,%7}, {%8,%9}, {%0,%1,%2,%3};\n"
        : "+f"(c[0]), "+f"(c[1]), "+f"(c[2]), "+f"(c[3])
        : "r"(a[0]), "r"(a[1]), "r"(a[2]), "r"(a[3]), "r"(b0), "r"(b1));
}
__device__ __forceinline__ void cp16(uint32_t dst, const void* src, bool p) {
    asm volatile("cp.async.cg.shared.global [%0], [%1], 16, %2;"
                 :: "r"(dst), "l"(src), "r"(p ? 16 : 0));
}
__device__ __forceinline__ void cp_commit() {
    asm volatile("cp.async.commit_group;");
}
template <int N> __device__ __forceinline__ void cp_wait() {
    asm volatile("cp.async.wait_group %0;" :: "n"(N));
}
__device__ __forceinline__ void ldsm4(uint32_t r[4], uint32_t a) {
    asm volatile("ldmatrix.sync.aligned.m8n8.x4.shared.b16 {%0,%1,%2,%3}, [%4];"
                 : "=r"(r[0]), "=r"(r[1]), "=r"(r[2]), "=r"(r[3]) : "r"(a));
}
__device__ __forceinline__ uint32_t pack_bf2(__nv_bfloat16 a, __nv_bfloat16 b) {
    __nv_bfloat162 t{a, b};
    return *reinterpret_cast<uint32_t*>(&t);
}
__device__ __forceinline__ uint32_t pack_h2(__half a, __half b) {
    __half2 t{a, b};
    return *reinterpret_cast<uint32_t*>(&t);
}

// ---------------- convert/split kernels ----------------
__global__ void conv_f16(const float4* __restrict__ src,
                         uint2* __restrict__ out, int n4)
{
    int i = blockIdx.x * blockDim.x + threadIdx.x;
    const int stride = gridDim.x * blockDim.x;
    for (; i < n4; i += stride) {
        float4 v = src[i];
        uint2 o;
        o.x = pack_h2(__float2half_rn(v.x), __float2half_rn(v.y));
        o.y = pack_h2(__float2half_rn(v.z), __float2half_rn(v.w));
        out[i] = o;
    }
}
// Wcomb: fp16 single + bf16 hi/lo pair, one pass
__global__ void split_wc(const float4* __restrict__ src,
                         uint2* __restrict__ w16,
                         uint2* __restrict__ hbf, uint2* __restrict__ lbf,
                         int n4)
{
    int i = blockIdx.x * blockDim.x + threadIdx.x;
    const int stride = gridDim.x * blockDim.x;
    for (; i < n4; i += stride) {
        float4 v = src[i];
        uint2 F;
        F.x = pack_h2(__float2half_rn(v.x), __float2half_rn(v.y));
        F.y = pack_h2(__float2half_rn(v.z), __float2half_rn(v.w));
        w16[i] = F;
        __nv_bfloat16 b0 = __float2bfloat16(v.x), b1 = __float2bfloat16(v.y);
        __nv_bfloat16 b2 = __float2bfloat16(v.z), b3 = __float2bfloat16(v.w);
        uint2 BH, BL;
        BH.x = pack_bf2(b0, b1);
        BH.y = pack_bf2(b2, b3);
        BL.x = pack_bf2(__float2bfloat16(v.x - __bfloat162float(b0)),
                        __float2bfloat16(v.y - __bfloat162float(b1)));
        BL.y = pack_bf2(__float2bfloat16(v.z - __bfloat162float(b2)),
                        __float2bfloat16(v.w - __bfloat162float(b3)));
        hbf[i] = BH;
        lbf[i] = BL;
    }
}

// ============================================================================
// gemmh<OUT>: C = relu(A @ W^T + bias). A, W fp16 [.,K]. Single term.
// OUT=0: C fp16. OUT=1: C bf16 hi/lo pair.
// 128x64 tile, BK=64, 4-stage ring, 8 warps (4M x 2N, warp 32x32).
// ============================================================================
#define BH_OFF 16384                // A: 128 rows x 128B; B: 64 rows x 128B
#define STAGEH 24576
#define SMEMH (4 * STAGEH)          // 98304

template <int OUT>
__global__ __launch_bounds__(256, 2)
void gemmh(const __half* __restrict__ A,
           const __half* __restrict__ W,
           const float* __restrict__ bias,
           __half* __restrict__ Cf16,
           __nv_bfloat16* __restrict__ Chi,
           __nv_bfloat16* __restrict__ Clo,
           int M, int N, int K)
{
    extern __shared__ __align__(1024) char smem[];
    const uint32_t sbase = (uint32_t)__cvta_generic_to_shared(smem);

    const int tid  = threadIdx.x;
    const int lane = tid & 31;
    const int wid  = tid >> 5;
    const int wm   = (wid & 3) * 32;
    const int wn   = (wid >> 2) * 32;
    const int bm   = blockIdx.y * 128;
    const int bn   = blockIdx.x * 64;

    const int lr8   = lane & 7;
    const int g     = lane >> 3;
    const int mrow  = (g & 1) * 8;
    const int kcolB = (g >> 1) * 16;

    uint32_t aRow[2], aXm[2], bRow[2], bXm[2];
    #pragma unroll
    for (int mi = 0; mi < 2; mi++) {
        const uint32_t rB = (uint32_t)(wm + mi * 16 + mrow + lr8) * 128;
        aRow[mi] = rB;
        aXm[mi]  = (rB >> 3) & 0x70;
    }
    #pragma unroll
    for (int p = 0; p < 2; p++) {
        const uint32_t rB = (uint32_t)(wn + p * 16 + mrow + lr8) * 128;
        bRow[p] = BH_OFF + rB;
        bXm[p]  = (rB >> 3) & 0x70;
    }

    float acc[2][4][4];
    #pragma unroll
    for (int i = 0; i < 2; i++)
        #pragma unroll
        for (int j = 0; j < 4; j++)
            #pragma unroll
            for (int v = 0; v < 4; v++) acc[i][j][v] = 0.f;

    const int nT = K / 64;

    auto stage = [&](int lt) {
        const uint32_t sb = sbase + (uint32_t)(lt & 3) * STAGEH;
        const int k0 = lt * 64;
        // A: 128 rows x 8 chunks = 1024, 4/thread
        #pragma unroll
        for (int i = 0; i < 4; i++) {
            const int lin = tid + i * 256;
            const int r = lin >> 3;
            const int c = lin & 7;
            const uint32_t off = (uint32_t)r * 128 + (uint32_t)c * 16;
            const uint32_t sw = off ^ ((off >> 3) & 0x70);
            const bool pa = (bm + r) < M;
            cp16(sb + sw, A + (size_t)(bm + r) * K + k0 + c * 8, pa);
        }
        // B: 64 rows x 8 chunks = 512, 2/thread
        #pragma unroll
        for (int i = 0; i < 2; i++) {
            const int lin = tid + i * 256;
            const int r = lin >> 3;
            const int c = lin & 7;
            const uint32_t off = (uint32_t)r * 128 + (uint32_t)c * 16;
            const uint32_t sw = off ^ ((off >> 3) & 0x70);
            cp16(sb + BH_OFF + sw, W + (size_t)(bn + r) * K + k0 + c * 8, true);
        }
        cp_commit();
    };

    stage(0);
    stage(1);
    stage(2);

    for (int kt = 0; kt < nT; kt++) {
        if (kt + 2 <= nT - 1)      cp_wait<2>();
        else if (kt + 1 <= nT - 1) cp_wait<1>();
        else                       cp_wait<0>();
        __syncthreads();
        if (kt + 3 < nT) stage(kt + 3);

        const uint32_t s0 = sbase + (uint32_t)(kt & 3) * STAGEH;

        #pragma unroll
        for (int ks = 0; ks < 64; ks += 16) {
            const uint32_t col = (uint32_t)(ks * 2) + kcolB;
            uint32_t ah[2][4], bh[2][4];
            #pragma unroll
            for (int mi = 0; mi < 2; mi++)
                ldsm4(ah[mi], s0 + aRow[mi] + (col ^ aXm[mi]));
            #pragma unroll
            for (int p = 0; p < 2; p++)
                ldsm4(bh[p], s0 + bRow[p] + (col ^ bXm[p]));
            #pragma unroll
            for (int mi = 0; mi < 2; mi++)
                #pragma unroll
                for (int ni = 0; ni < 4; ni++) {
                    const int p = ni >> 1, q = ni & 1;
                    mma_fp16(acc[mi][ni], ah[mi], bh[p][q], bh[p][q + 2]);
                }
        }
    }

    const int lq = (lane & 3) * 2;
    const int lr = lane >> 2;
    #pragma unroll
    for (int mi = 0; mi < 2; mi++) {
        #pragma unroll
        for (int ni = 0; ni < 4; ni++) {
            const int m0 = bm + wm + mi * 16 + lr;
            const int n  = bn + wn + ni * 8 + lq;
            const float bv0 = __ldg(bias + n), bv1 = __ldg(bias + n + 1);
            #pragma unroll
            for (int h = 0; h < 2; h++) {
                const int m = m0 + h * 8;
                if (m < M) {
                    float x0 = fmaxf(acc[mi][ni][2 * h]     + bv0, 0.f);
                    float x1 = fmaxf(acc[mi][ni][2 * h + 1] + bv1, 0.f);
                    if (OUT == 0) {
                        *reinterpret_cast<uint32_t*>(Cf16 + (size_t)m * N + n) =
                            pack_h2(__float2half_rn(x0), __float2half_rn(x1));
                    } else {
                        __nv_bfloat16 h0 = __float2bfloat16(x0);
                        __nv_bfloat16 h1 = __float2bfloat16(x1);
                        __nv_bfloat16 l0 = __float2bfloat16(x0 - __bfloat162float(h0));
                        __nv_bfloat16 l1 = __float2bfloat16(x1 - __bfloat162float(h1));
                        *reinterpret_cast<uint32_t*>(Chi + (size_t)m * N + n) = pack_bf2(h0, h1);
                        *reinterpret_cast<uint32_t*>(Clo + (size_t)m * N + n) = pack_bf2(l0, l1);
                    }
                }
            }
        }
    }
}

// ============================================================================
// gemm_small_fused: bf16x3 split-K(4) with fused finalize (R12-proven).
// ============================================================================
#define A_T3 4096
#define STAGE3 12288
#define SMEM3 (3 * STAGE3)

__global__ __launch_bounds__(128, 4)
void gemm_small_fused(const __nv_bfloat16* __restrict__ Ahi,
                      const __nv_bfloat16* __restrict__ Alo,
                      const __nv_bfloat16* __restrict__ Whi,
                      const __nv_bfloat16* __restrict__ Wlo,
                      const float* __restrict__ bias,
                      float* __restrict__ part,
                      unsigned* __restrict__ ticket,
                      __nv_bfloat16* __restrict__ Chi,
                      __nv_bfloat16* __restrict__ Clo,
                      int M, int N, int K)
{
    extern __shared__ __align__(1024) char smem[];
    const uint32_t sbase = (uint32_t)__cvta_generic_to_shared(smem);

    const int tid  = threadIdx.x;
    const int lane = tid & 31;
    const int wid  = tid >> 5;
    const int wm   = (wid & 1) * 16;
    const int wn   = (wid >> 1) * 32;
    const int bm   = blockIdx.y * 32;
    const int bn   = blockIdx.x * 64;
    const int kbase = blockIdx.z * (K / KSPLIT);

    const int lr8   = lane & 7;
    const int g     = lane >> 3;
    const int mrow  = (g & 1) * 8;
    const int kcolB = (g >> 1) * 16;

    uint32_t aRowB, aXm, bRow[2], bXm[2];
    {
        const uint32_t rB = (uint32_t)(wm + mrow + lr8) * 128;
        aRowB = rB;
        aXm   = (rB >> 3) & 0x70;
    }
    #pragma unroll
    for (int p = 0; p < 2; p++) {
        const uint32_t rB = (uint32_t)(wn + p * 16 + mrow + lr8) * 128;
        bRow[p] = A_T3 + rB;
        bXm[p]  = (rB >> 3) & 0x70;
    }

    float acc[4][4];
    #pragma unroll
    for (int j = 0; j < 4; j++)
        #pragma unroll
        for (int v = 0; v < 4; v++) acc[j][v] = 0.f;

    const int nT = (K / KSPLIT) / 32;

    auto stage = [&](int lt) {
        const uint32_t sb = sbase + (uint32_t)(lt % 3) * STAGE3;
        const int k0 = kbase + lt * 32;
        #pragma unroll
        for (int i = 0; i < 2; i++) {
            const int lin = tid + i * 128;
            const int r = lin >> 3;
            const int c = lin & 7;
            const uint32_t off = (uint32_t)r * 128 + (uint32_t)c * 16;
            const uint32_t sw = off ^ ((off >> 3) & 0x70);
            const bool pa = (bm + r) < M;
            const __nv_bfloat16* src = (c < 4) ? Ahi : Alo;
            cp16(sb + sw, src + (size_t)(bm + r) * K + k0 + (c & 3) * 8, pa);
        }
        #pragma unroll
        for (int i = 0; i < 4; i++) {
            const int lin = tid + i * 128;
            const int r = lin >> 3;
            const int c = lin & 7;
            const uint32_t off = (uint32_t)r * 128 + (uint32_t)c * 16;
            const uint32_t sw = off ^ ((off >> 3) & 0x70);
            const __nv_bfloat16* src = (c < 4) ? Whi : Wlo;
            cp16(sb + A_T3 + sw, src + (size_t)(bn + r) * K + k0 + (c & 3) * 8, true);
        }
        cp_commit();
    };

    stage(0);
    stage(1);

    for (int kt = 0; kt < nT; kt++) {
        if (kt + 1 < nT) cp_wait<1>();
        else             cp_wait<0>();
        __syncthreads();
        if (kt + 2 < nT) stage(kt + 2);

        const uint32_t s0 = sbase + (uint32_t)(kt % 3) * STAGE3;

        #pragma unroll
        for (int ks = 0; ks < 32; ks += 16) {
            const uint32_t colH = (uint32_t)(ks * 2) + kcolB;
            const uint32_t colL = 64u + (uint32_t)(ks * 2) + kcolB;
            uint32_t ah[4], al[4], bh[2][4], bl[2][4];
            ldsm4(ah, s0 + aRowB + (colH ^ aXm));
            ldsm4(al, s0 + aRowB + (colL ^ aXm));
            #pragma unroll
            for (int p = 0; p < 2; p++) {
                ldsm4(bh[p], s0 + bRow[p] + (colH ^ bXm[p]));
                ldsm4(bl[p], s0 + bRow[p] + (colL ^ bXm[p]));
            }
            #pragma unroll
            for (int ni = 0; ni < 4; ni++) {
                const int p = ni >> 1, q = ni & 1;
                mma_bf16(acc[ni], ah, bh[p][q], bh[p][q + 2]);
                mma_bf16(acc[ni], ah, bl[p][q], bl[p][q + 2]);
                mma_bf16(acc[ni], al, bh[p][q], bh[p][q + 2]);
            }
        }
    }

    const int lq = (lane & 3) * 2;
    const int lr = lane >> 2;
    #pragma unroll
    for (int ni = 0; ni < 4; ni++) {
        const int m0 = bm + wm + lr;
        const int n  = bn + wn + ni * 8 + lq;
        #pragma unroll
        for (int h = 0; h < 2; h++) {
            const int m = m0 + h * 8;
            if (m < M) {
                float* dst = part + ((size_t)blockIdx.z * M + m) * N + n;
                dst[0] = acc[ni][2 * h];
                dst[1] = acc[ni][2 * h + 1];
            }
        }
    }

    __threadfence();
    __syncthreads();
    __shared__ unsigned s_old;
    const int tileId = (int)blockIdx.y * (int)gridDim.x + (int)blockIdx.x;
    if (tid == 0) s_old = atomicAdd(&ticket[tileId], 1u);
    __syncthreads();
    if (s_old == KSPLIT - 1) {
        __threadfence();
        for (int idx = tid * 2; idx < 32 * 64; idx += 256) {
            const int lm = idx >> 6;
            const int ln = idx & 63;
            const int m = bm + lm;
            if (m >= M) break;
            const int n = bn + ln;
            float s0 = 0.f, s1 = 0.f;
            #pragma unroll
            for (int z = 0; z < KSPLIT; z++) {
                const float* p = part + ((size_t)z * M + m) * N + n;
                s0 += p[0];
                s1 += p[1];
            }
            float x0 = fmaxf(s0 + __ldg(bias + n), 0.f);
            float x1 = fmaxf(s1 + __ldg(bias + n + 1), 0.f);
            __nv_bfloat16 h0 = __float2bfloat16(x0);
            __nv_bfloat16 h1 = __float2bfloat16(x1);
            __nv_bfloat16 l0 = __float2bfloat16(x0 - __bfloat162float(h0));
            __nv_bfloat16 l1 = __float2bfloat16(x1 - __bfloat162float(h1));
            *reinterpret_cast<uint32_t*>(Chi + (size_t)m * N + n) = pack_bf2(h0, h1);
            *reinterpret_cast<uint32_t*>(Clo + (size_t)m * N + n) = pack_bf2(l0, l1);
        }
        if (tid == 0) ticket[tileId] = 0;
    }
}

// Root projection
__global__ void proj_kernel(const __nv_bfloat16* __restrict__ hhi,
                            const __nv_bfloat16* __restrict__ hlo,
                            const float* __restrict__ Wp,
                            const float* __restrict__ bp,
                            float* __restrict__ out)
{
    const int w    = threadIdx.x >> 5;
    const int lane = threadIdx.x & 31;
    float s = 0.f;
    for (int k = lane; k < 512; k += 32) {
        const float hv = __bfloat162float(hhi[k]) + __bfloat162float(hlo[k]);
        s = fmaf(hv, Wp[w * 512 + k], s);
    }
    #pragma unroll
    for (int o = 16; o > 0; o >>= 1)
        s += __shfl_xor_sync(0xffffffffu, s, o);
    if (lane == 0) out[w] = s + bp[w];
}

extern "C" void kernel_launch(void* const* d_in, const int* in_sizes, int n_in,
                              void* d_out, int out_size)
{
    const float* leaf  = (const float*)d_in[0];
    const float* Wemb  = (const float*)d_in[1];
    const float* bemb  = (const float*)d_in[2];
    const float* Wcomb = (const float*)d_in[3];
    const float* bcomb = (const float*)d_in[4];
    const float* Wproj = (const float*)d_in[5];
    const float* bproj = (const float*)d_in[6];
    float* out = (float*)d_out;

    __half *leaf16, *We16, *Wc16, *P16, *Q16;
    __nv_bfloat16 *Wcb_h, *Wcb_l, *hB, *lB, *hC, *lC;
    float* part;
    unsigned* ticket;
    cudaGetSymbolAddress((void**)&leaf16, g_leaf16);
    cudaGetSymbolAddress((void**)&We16, g_We16);
    cudaGetSymbolAddress((void**)&Wc16, g_Wc16);
    cudaGetSymbolAddress((void**)&Wcb_h, g_Wcb_h);
    cudaGetSymbolAddress((void**)&Wcb_l, g_Wcb_l);
    cudaGetSymbolAddress((void**)&P16, g_P16);
    cudaGetSymbolAddress((void**)&Q16, g_Q16);
    cudaGetSymbolAddress((void**)&hB, g_hB);
    cudaGetSymbolAddress((void**)&lB, g_lB);
    cudaGetSymbolAddress((void**)&hC, g_hC);
    cudaGetSymbolAddress((void**)&lC, g_lC);
    cudaGetSymbolAddress((void**)&part, g_part);
    cudaGetSymbolAddress((void**)&ticket, g_ticket);

    cudaFuncSetAttribute(gemmh<0>,
                         cudaFuncAttributeMaxDynamicSharedMemorySize, SMEMH);
    cudaFuncSetAttribute(gemmh<1>,
                         cudaFuncAttributeMaxDynamicSharedMemorySize, SMEMH);
    cudaFuncSetAttribute(gemm_small_fused,
                         cudaFuncAttributeMaxDynamicSharedMemorySize, SMEM3);

    // ---- convert/split inputs ----
    conv_f16<<<4096, 256>>>((const float4*)leaf, (uint2*)leaf16, 8192 * 4096 / 4);
    conv_f16<<<512, 256>>>((const float4*)Wemb, (uint2*)We16, 512 * 4096 / 4);
    split_wc<<<128, 256>>>((const float4*)Wcomb, (uint2*)Wc16,
                           (uint2*)Wcb_h, (uint2*)Wcb_l, 512 * 1024 / 4);

    // ---- leaf -> P16 ----
    {
        dim3 grid(512 / 64, 8192 / 128);
        gemmh<0><<<grid, 256, SMEMH>>>(leaf16, We16, bemb,
                                       P16, nullptr, nullptr, 8192, 512, 4096);
    }
    // ---- m = 4096 -> Q16, m = 2048 -> P16, m = 1024 -> bf16 pair ----
    {
        dim3 grid(512 / 64, 4096 / 128);
        gemmh<0><<<grid, 256, SMEMH>>>(P16, Wc16, bcomb,
                                       Q16, nullptr, nullptr, 4096, 512, 1024);
    }
    {
        dim3 grid(512 / 64, 2048 / 128);
        gemmh<0><<<grid, 256, SMEMH>>>(Q16, Wc16, bcomb,
                                       P16, nullptr, nullptr, 2048, 512, 1024);
    }
    {
        dim3 grid(512 / 64, 1024 / 128);
        gemmh<1><<<grid, 256, SMEMH>>>(P16, Wc16, bcomb,
                                       nullptr, hB, lB, 1024, 512, 1024);
    }

    // ---- tail m = 512..1: split-K with fused finalize ----
    __nv_bfloat16 *cur_h = hB, *cur_l = lB, *nxt_h = hC, *nxt_l = lC;
    for (int m = 512; m >= 1; m >>= 1) {
        dim3 grid(512 / 64, (m + 31) / 32, KSPLIT);
        gemm_small_fused<<<grid, 128, SMEM3>>>(cur_h, cur_l, Wcb_h, Wcb_l,
                                               bcomb, part, ticket,
                                               nxt_h, nxt_l, m, 512, 1024);
        __nv_bfloat16* t;
        t = cur_h; cur_h = nxt_h; nxt_h = t;
        t = cur_l; cur_l = nxt_l; nxt_l = t;
    }

    proj_kernel<<<1, 64>>>(cur_h, cur_l, Wproj, bproj, out);
}

// round 14
// speedup vs baseline: 2.1979x; 1.0501x over previous
#include <cuda_runtime.h>
#include <cuda_bf16.h>
#include <cuda_fp16.h>
#include <cstdint>

// Tree-RNN GEMMs on mma.sync tensor cores.
// Leaf + m=4096: fp16 single-term, 128x128 tile (warp 32x64, MMA:LDSM=16:6).
// m=2048/1024:  fp16 single-term, 128x64 tile (R13-proven).
// Tail (m<=512): bf16x3 split-K(4) with fused finalize (R12-proven).

// ---------------- device scratch (no allocation allowed) ----------------
__device__ __half g_leaf16[8192ull * 4096];          // 64 MB
__device__ __half g_We16[512 * 4096];
__device__ __half g_Wc16[512 * 1024];
__device__ __nv_bfloat16 g_Wcb_h[512 * 1024], g_Wcb_l[512 * 1024];
__device__ __half g_P16[8192 * 512];
__device__ __half g_Q16[4096 * 512];
__device__ __nv_bfloat16 g_hB[1024 * 512], g_lB[1024 * 512];
__device__ __nv_bfloat16 g_hC[512 * 512],  g_lC[512 * 512];
#define KSPLIT 4
__device__ float g_part[KSPLIT * 512 * 512];
__device__ unsigned g_ticket[128];

// ---------------- PTX helpers ----------------
__device__ __forceinline__ void mma_bf16(float c[4], const uint32_t a[4],
                                         const uint32_t b0, const uint32_t b1) {
    asm volatile(
        "mma.sync.aligned.m16n8k16.row.col.f32.bf16.bf16.f32 "
        "{%0,%1,%2,%3}, {%4,%5,%6,%7}, {%8,%9}, {%0,%1,%2,%3};\n"
        : "+f"(c[0]), "+f"(c[1]), "+f"(c[2]), "+f"(c[3])
        : "r"(a[0]), "r"(a[1]), "r"(a[2]), "r"(a[3]), "r"(b0), "r"(b1));
}
__device__ __forceinline__ void mma_fp16(float c[4], const uint32_t a[4],
                                         const uint32_t b0, const uint32_t b1) {
    asm volatile(
        "mma.sync.aligned.m16n8k16.row.col.f32.f16.f16.f32 "
        "{%0,%1,%2,%3}, {%4,%5,%6,%7}, {%8,%9}, {%0,%1,%2,%3};\n"
        : "+f"(c[0]), "+f"(c[1]), "+f"(c[2]), "+f"(c[3])
        : "r"(a[0]), "r"(a[1]), "r"(a[2]), "r"(a[3]), "r"(b0), "r"(b1));
}
__device__ __forceinline__ void cp16(uint32_t dst, const void* src, bool p) {
    asm volatile("cp.async.cg.shared.global [%0], [%1], 16, %2;"
                 :: "r"(dst), "l"(src), "r"(p ? 16 : 0));
}
__device__ __forceinline__ void cp_commit() {
    asm volatile("cp.async.commit_group;");
}
template <int N> __device__ __forceinline__ void cp_wait() {
    asm volatile("cp.async.wait_group %0;" :: "n"(N));
}
__device__ __forceinline__ void ldsm4(uint32_t r[4], uint32_t a) {
    asm volatile("ldmatrix.sync.aligned.m8n8.x4.shared.b16 {%0,%1,%2,%3}, [%4];"
                 : "=r"(r[0]), "=r"(r[1]), "=r"(r[2]), "=r"(r[3]) : "r"(a));
}
__device__ __forceinline__ uint32_t pack_bf2(__nv_bfloat16 a, __nv_bfloat16 b) {
    __nv_bfloat162 t{a, b};
    return *reinterpret_cast<uint32_t*>(&t);
}
__device__ __forceinline__ uint32_t pack_h2(__half a, __half b) {
    __half2 t{a, b};
    return *reinterpret_cast<uint32_t*>(&t);
}

// ---------------- convert/split kernels ----------------
__global__ void conv_f16(const float4* __restrict__ src,
                         uint2* __restrict__ out, int n4)
{
    int i = blockIdx.x * blockDim.x + threadIdx.x;
    const int stride = gridDim.x * blockDim.x;
    for (; i < n4; i += stride) {
        float4 v = src[i];
        uint2 o;
        o.x = pack_h2(__float2half_rn(v.x), __float2half_rn(v.y));
        o.y = pack_h2(__float2half_rn(v.z), __float2half_rn(v.w));
        out[i] = o;
    }
}
__global__ void split_wc(const float4* __restrict__ src,
                         uint2* __restrict__ w16,
                         uint2* __restrict__ hbf, uint2* __restrict__ lbf,
                         int n4)
{
    int i = blockIdx.x * blockDim.x + threadIdx.x;
    const int stride = gridDim.x * blockDim.x;
    for (; i < n4; i += stride) {
        float4 v = src[i];
        uint2 F;
        F.x = pack_h2(__float2half_rn(v.x), __float2half_rn(v.y));
        F.y = pack_h2(__float2half_rn(v.z), __float2half_rn(v.w));
        w16[i] = F;
        __nv_bfloat16 b0 = __float2bfloat16(v.x), b1 = __float2bfloat16(v.y);
        __nv_bfloat16 b2 = __float2bfloat16(v.z), b3 = __float2bfloat16(v.w);
        uint2 BH, BL;
        BH.x = pack_bf2(b0, b1);
        BH.y = pack_bf2(b2, b3);
        BL.x = pack_bf2(__float2bfloat16(v.x - __bfloat162float(b0)),
                        __float2bfloat16(v.y - __bfloat162float(b1)));
        BL.y = pack_bf2(__float2bfloat16(v.z - __bfloat162float(b2)),
                        __float2bfloat16(v.w - __bfloat162float(b3)));
        hbf[i] = BH;
        lbf[i] = BL;
    }
}

// ============================================================================
// gemmh128: fp16 single-term, 128x128 CTA tile, warp tile 32x64 (4Mx2N).
// 3-stage ring (32 KB/stage), prefetch distance 2. OUT=0 fp16 out only.
// ============================================================================
#define B128_OFF 16384
#define STAGE128 32768
#define SMEM128 (3 * STAGE128)      // 98304

__global__ __launch_bounds__(256, 2)
void gemmh128(const __half* __restrict__ A,
              const __half* __restrict__ W,
              const float* __restrict__ bias,
              __half* __restrict__ Cf16,
              int M, int N, int K)
{
    extern __shared__ __align__(1024) char smem[];
    const uint32_t sbase = (uint32_t)__cvta_generic_to_shared(smem);

    const int tid  = threadIdx.x;
    const int lane = tid & 31;
    const int wid  = tid >> 5;
    const int wm   = (wid & 3) * 32;
    const int wn   = (wid >> 2) * 64;
    const int bm   = blockIdx.y * 128;
    const int bn   = blockIdx.x * 128;

    const int lr8   = lane & 7;
    const int g     = lane >> 3;
    const int mrow  = (g & 1) * 8;
    const int kcolB = (g >> 1) * 16;

    uint32_t aRow[2], aXm[2], bRow[4], bXm[4];
    #pragma unroll
    for (int mi = 0; mi < 2; mi++) {
        const uint32_t rB = (uint32_t)(wm + mi * 16 + mrow + lr8) * 128;
        aRow[mi] = rB;
        aXm[mi]  = (rB >> 3) & 0x70;
    }
    #pragma unroll
    for (int p = 0; p < 4; p++) {
        const uint32_t rB = (uint32_t)(wn + p * 16 + mrow + lr8) * 128;
        bRow[p] = B128_OFF + rB;
        bXm[p]  = (rB >> 3) & 0x70;
    }

    float acc[2][8][4];
    #pragma unroll
    for (int i = 0; i < 2; i++)
        #pragma unroll
        for (int j = 0; j < 8; j++)
            #pragma unroll
            for (int v = 0; v < 4; v++) acc[i][j][v] = 0.f;

    const int nT = K / 64;

    auto stage = [&](int lt) {
        const uint32_t sb = sbase + (uint32_t)(lt % 3) * STAGE128;
        const int k0 = lt * 64;
        // A: 128 rows x 8 chunks = 1024, 4/thread
        #pragma unroll
        for (int i = 0; i < 4; i++) {
            const int lin = tid + i * 256;
            const int r = lin >> 3;
            const int c = lin & 7;
            const uint32_t off = (uint32_t)r * 128 + (uint32_t)c * 16;
            const uint32_t sw = off ^ ((off >> 3) & 0x70);
            const bool pa = (bm + r) < M;
            cp16(sb + sw, A + (size_t)(bm + r) * K + k0 + c * 8, pa);
        }
        // B: 128 rows x 8 chunks = 1024, 4/thread
        #pragma unroll
        for (int i = 0; i < 4; i++) {
            const int lin = tid + i * 256;
            const int r = lin >> 3;
            const int c = lin & 7;
            const uint32_t off = (uint32_t)r * 128 + (uint32_t)c * 16;
            const uint32_t sw = off ^ ((off >> 3) & 0x70);
            cp16(sb + B128_OFF + sw, W + (size_t)(bn + r) * K + k0 + c * 8, true);
        }
        cp_commit();
    };

    stage(0);
    stage(1);

    for (int kt = 0; kt < nT; kt++) {
        if (kt + 1 < nT) cp_wait<1>();
        else             cp_wait<0>();
        __syncthreads();
        if (kt + 2 < nT) stage(kt + 2);

        const uint32_t s0 = sbase + (uint32_t)(kt % 3) * STAGE128;

        #pragma unroll
        for (int ks = 0; ks < 64; ks += 16) {
            const uint32_t col = (uint32_t)(ks * 2) + kcolB;
            uint32_t ah[2][4];
            #pragma unroll
            for (int mi = 0; mi < 2; mi++)
                ldsm4(ah[mi], s0 + aRow[mi] + (col ^ aXm[mi]));
            #pragma unroll
            for (int p = 0; p < 4; p++) {
                uint32_t bh[4];
                ldsm4(bh, s0 + bRow[p] + (col ^ bXm[p]));
                // bh = { b(2p)k0, b(2p+1)k0, b(2p)k8, b(2p+1)k8 }
                #pragma unroll
                for (int mi = 0; mi < 2; mi++) {
                    mma_fp16(acc[mi][2 * p],     ah[mi], bh[0], bh[2]);
                    mma_fp16(acc[mi][2 * p + 1], ah[mi], bh[1], bh[3]);
                }
            }
        }
    }

    const int lq = (lane & 3) * 2;
    const int lr = lane >> 2;
    #pragma unroll
    for (int mi = 0; mi < 2; mi++) {
        #pragma unroll
        for (int ni = 0; ni < 8; ni++) {
            const int m0 = bm + wm + mi * 16 + lr;
            const int n  = bn + wn + ni * 8 + lq;
            const float bv0 = __ldg(bias + n), bv1 = __ldg(bias + n + 1);
            #pragma unroll
            for (int h = 0; h < 2; h++) {
                const int m = m0 + h * 8;
                if (m < M) {
                    float x0 = fmaxf(acc[mi][ni][2 * h]     + bv0, 0.f);
                    float x1 = fmaxf(acc[mi][ni][2 * h + 1] + bv1, 0.f);
                    *reinterpret_cast<uint32_t*>(Cf16 + (size_t)m * N + n) =
                        pack_h2(__float2half_rn(x0), __float2half_rn(x1));
                }
            }
        }
    }
}

// ============================================================================
// gemmh<OUT>: fp16 single-term, 128x64 tile (R13-proven).
// OUT=0: C fp16. OUT=1: C bf16 hi/lo pair.
// ============================================================================
#define BH_OFF 16384
#define STAGEH 24576
#define SMEMH (4 * STAGEH)

template <int OUT>
__global__ __launch_bounds__(256, 2)
void gemmh(const __half* __restrict__ A,
           const __half* __restrict__ W,
           const float* __restrict__ bias,
           __half* __restrict__ Cf16,
           __nv_bfloat16* __restrict__ Chi,
           __nv_bfloat16* __restrict__ Clo,
           int M, int N, int K)
{
    extern __shared__ __align__(1024) char smem[];
    const uint32_t sbase = (uint32_t)__cvta_generic_to_shared(smem);

    const int tid  = threadIdx.x;
    const int lane = tid & 31;
    const int wid  = tid >> 5;
    const int wm   = (wid & 3) * 32;
    const int wn   = (wid >> 2) * 32;
    const int bm   = blockIdx.y * 128;
    const int bn   = blockIdx.x * 64;

    const int lr8   = lane & 7;
    const int g     = lane >> 3;
    const int mrow  = (g & 1) * 8;
    const int kcolB = (g >> 1) * 16;

    uint32_t aRow[2], aXm[2], bRow[2], bXm[2];
    #pragma unroll
    for (int mi = 0; mi < 2; mi++) {
        const uint32_t rB = (uint32_t)(wm + mi * 16 + mrow + lr8) * 128;
        aRow[mi] = rB;
        aXm[mi]  = (rB >> 3) & 0x70;
    }
    #pragma unroll
    for (int p = 0; p < 2; p++) {
        const uint32_t rB = (uint32_t)(wn + p * 16 + mrow + lr8) * 128;
        bRow[p] = BH_OFF + rB;
        bXm[p]  = (rB >> 3) & 0x70;
    }

    float acc[2][4][4];
    #pragma unroll
    for (int i = 0; i < 2; i++)
        #pragma unroll
        for (int j = 0; j < 4; j++)
            #pragma unroll
            for (int v = 0; v < 4; v++) acc[i][j][v] = 0.f;

    const int nT = K / 64;

    auto stage = [&](int lt) {
        const uint32_t sb = sbase + (uint32_t)(lt & 3) * STAGEH;
        const int k0 = lt * 64;
        #pragma unroll
        for (int i = 0; i < 4; i++) {
            const int lin = tid + i * 256;
            const int r = lin >> 3;
            const int c = lin & 7;
            const uint32_t off = (uint32_t)r * 128 + (uint32_t)c * 16;
            const uint32_t sw = off ^ ((off >> 3) & 0x70);
            const bool pa = (bm + r) < M;
            cp16(sb + sw, A + (size_t)(bm + r) * K + k0 + c * 8, pa);
        }
        #pragma unroll
        for (int i = 0; i < 2; i++) {
            const int lin = tid + i * 256;
            const int r = lin >> 3;
            const int c = lin & 7;
            const uint32_t off = (uint32_t)r * 128 + (uint32_t)c * 16;
            const uint32_t sw = off ^ ((off >> 3) & 0x70);
            cp16(sb + BH_OFF + sw, W + (size_t)(bn + r) * K + k0 + c * 8, true);
        }
        cp_commit();
    };

    stage(0);
    stage(1);
    stage(2);

    for (int kt = 0; kt < nT; kt++) {
        if (kt + 2 <= nT - 1)      cp_wait<2>();
        else if (kt + 1 <= nT - 1) cp_wait<1>();
        else                       cp_wait<0>();
        __syncthreads();
        if (kt + 3 < nT) stage(kt + 3);

        const uint32_t s0 = sbase + (uint32_t)(kt & 3) * STAGEH;

        #pragma unroll
        for (int ks = 0; ks < 64; ks += 16) {
            const uint32_t col = (uint32_t)(ks * 2) + kcolB;
            uint32_t ah[2][4], bh[2][4];
            #pragma unroll
            for (int mi = 0; mi < 2; mi++)
                ldsm4(ah[mi], s0 + aRow[mi] + (col ^ aXm[mi]));
            #pragma unroll
            for (int p = 0; p < 2; p++)
                ldsm4(bh[p], s0 + bRow[p] + (col ^ bXm[p]));
            #pragma unroll
            for (int mi = 0; mi < 2; mi++)
                #pragma unroll
                for (int ni = 0; ni < 4; ni++) {
                    const int p = ni >> 1, q = ni & 1;
                    mma_fp16(acc[mi][ni], ah[mi], bh[p][q], bh[p][q + 2]);
                }
        }
    }

    const int lq = (lane & 3) * 2;
    const int lr = lane >> 2;
    #pragma unroll
    for (int mi = 0; mi < 2; mi++) {
        #pragma unroll
        for (int ni = 0; ni < 4; ni++) {
            const int m0 = bm + wm + mi * 16 + lr;
            const int n  = bn + wn + ni * 8 + lq;
            const float bv0 = __ldg(bias + n), bv1 = __ldg(bias + n + 1);
            #pragma unroll
            for (int h = 0; h < 2; h++) {
                const int m = m0 + h * 8;
                if (m < M) {
                    float x0 = fmaxf(acc[mi][ni][2 * h]     + bv0, 0.f);
                    float x1 = fmaxf(acc[mi][ni][2 * h + 1] + bv1, 0.f);
                    if (OUT == 0) {
                        *reinterpret_cast<uint32_t*>(Cf16 + (size_t)m * N + n) =
                            pack_h2(__float2half_rn(x0), __float2half_rn(x1));
                    } else {
                        __nv_bfloat16 h0 = __float2bfloat16(x0);
                        __nv_bfloat16 h1 = __float2bfloat16(x1);
                        __nv_bfloat16 l0 = __float2bfloat16(x0 - __bfloat162float(h0));
                        __nv_bfloat16 l1 = __float2bfloat16(x1 - __bfloat162float(h1));
                        *reinterpret_cast<uint32_t*>(Chi + (size_t)m * N + n) = pack_bf2(h0, h1);
                        *reinterpret_cast<uint32_t*>(Clo + (size_t)m * N + n) = pack_bf2(l0, l1);
                    }
                }
            }
        }
    }
}

// ============================================================================
// gemm_small_fused: bf16x3 split-K(4) with fused finalize (R12-proven).
// ============================================================================
#define A_T3 4096
#define STAGE3 12288
#define SMEM3 (3 * STAGE3)

__global__ __launch_bounds__(128, 4)
void gemm_small_fused(const __nv_bfloat16* __restrict__ Ahi,
                      const __nv_bfloat16* __restrict__ Alo,
                      const __nv_bfloat16* __restrict__ Whi,
                      const __nv_bfloat16* __restrict__ Wlo,
                      const float* __restrict__ bias,
                      float* __restrict__ part,
                      unsigned* __restrict__ ticket,
                      __nv_bfloat16* __restrict__ Chi,
                      __nv_bfloat16* __restrict__ Clo,
                      int M, int N, int K)
{
    extern __shared__ __align__(1024) char smem[];
    const uint32_t sbase = (uint32_t)__cvta_generic_to_shared(smem);

    const int tid  = threadIdx.x;
    const int lane = tid & 31;
    const int wid  = tid >> 5;
    const int wm   = (wid & 1) * 16;
    const int wn   = (wid >> 1) * 32;
    const int bm   = blockIdx.y * 32;
    const int bn   = blockIdx.x * 64;
    const int kbase = blockIdx.z * (K / KSPLIT);

    const int lr8   = lane & 7;
    const int g     = lane >> 3;
    const int mrow  = (g & 1) * 8;
    const int kcolB = (g >> 1) * 16;

    uint32_t aRowB, aXm, bRow[2], bXm[2];
    {
        const uint32_t rB = (uint32_t)(wm + mrow + lr8) * 128;
        aRowB = rB;
        aXm   = (rB >> 3) & 0x70;
    }
    #pragma unroll
    for (int p = 0; p < 2; p++) {
        const uint32_t rB = (uint32_t)(wn + p * 16 + mrow + lr8) * 128;
        bRow[p] = A_T3 + rB;
        bXm[p]  = (rB >> 3) & 0x70;
    }

    float acc[4][4];
    #pragma unroll
    for (int j = 0; j < 4; j++)
        #pragma unroll
        for (int v = 0; v < 4; v++) acc[j][v] = 0.f;

    const int nT = (K / KSPLIT) / 32;

    auto stage = [&](int lt) {
        const uint32_t sb = sbase + (uint32_t)(lt % 3) * STAGE3;
        const int k0 = kbase + lt * 32;
        #pragma unroll
        for (int i = 0; i < 2; i++) {
            const int lin = tid + i * 128;
            const int r = lin >> 3;
            const int c = lin & 7;
            const uint32_t off = (uint32_t)r * 128 + (uint32_t)c * 16;
            const uint32_t sw = off ^ ((off >> 3) & 0x70);
            const bool pa = (bm + r) < M;
            const __nv_bfloat16* src = (c < 4) ? Ahi : Alo;
            cp16(sb + sw, src + (size_t)(bm + r) * K + k0 + (c & 3) * 8, pa);
        }
        #pragma unroll
        for (int i = 0; i < 4; i++) {
            const int lin = tid + i * 128;
            const int r = lin >> 3;
            const int c = lin & 7;
            const uint32_t off = (uint32_t)r * 128 + (uint32_t)c * 16;
            const uint32_t sw = off ^ ((off >> 3) & 0x70);
            const __nv_bfloat16* src = (c < 4) ? Whi : Wlo;
            cp16(sb + A_T3 + sw, src + (size_t)(bn + r) * K + k0 + (c & 3) * 8, true);
        }
        cp_commit();
    };

    stage(0);
    stage(1);

    for (int kt = 0; kt < nT; kt++) {
        if (kt + 1 < nT) cp_wait<1>();
        else             cp_wait<0>();
        __syncthreads();
        if (kt + 2 < nT) stage(kt + 2);

        const uint32_t s0 = sbase + (uint32_t)(kt % 3) * STAGE3;

        #pragma unroll
        for (int ks = 0; ks < 32; ks += 16) {
            const uint32_t colH = (uint32_t)(ks * 2) + kcolB;
            const uint32_t colL = 64u + (uint32_t)(ks * 2) + kcolB;
            uint32_t ah[4], al[4], bh[2][4], bl[2][4];
            ldsm4(ah, s0 + aRowB + (colH ^ aXm));
            ldsm4(al, s0 + aRowB + (colL ^ aXm));
            #pragma unroll
            for (int p = 0; p < 2; p++) {
                ldsm4(bh[p], s0 + bRow[p] + (colH ^ bXm[p]));
                ldsm4(bl[p], s0 + bRow[p] + (colL ^ bXm[p]));
            }
            #pragma unroll
            for (int ni = 0; ni < 4; ni++) {
                const int p = ni >> 1, q = ni & 1;
                mma_bf16(acc[ni], ah, bh[p][q], bh[p][q + 2]);
                mma_bf16(acc[ni], ah, bl[p][q], bl[p][q + 2]);
                mma_bf16(acc[ni], al, bh[p][q], bh[p][q + 2]);
            }
        }
    }

    const int lq = (lane & 3) * 2;
    const int lr = lane >> 2;
    #pragma unroll
    for (int ni = 0; ni < 4; ni++) {
        const int m0 = bm + wm + lr;
        const int n  = bn + wn + ni * 8 + lq;
        #pragma unroll
        for (int h = 0; h < 2; h++) {
            const int m = m0 + h * 8;
            if (m < M) {
                float* dst = part + ((size_t)blockIdx.z * M + m) * N + n;
                dst[0] = acc[ni][2 * h];
                dst[1] = acc[ni][2 * h + 1];
            }
        }
    }

    __threadfence();
    __syncthreads();
    __shared__ unsigned s_old;
    const int tileId = (int)blockIdx.y * (int)gridDim.x + (int)blockIdx.x;
    if (tid == 0) s_old = atomicAdd(&ticket[tileId], 1u);
    __syncthreads();
    if (s_old == KSPLIT - 1) {
        __threadfence();
        for (int idx = tid * 2; idx < 32 * 64; idx += 256) {
            const int lm = idx >> 6;
            const int ln = idx & 63;
            const int m = bm + lm;
            if (m >= M) break;
            const int n = bn + ln;
            float s0 = 0.f, s1 = 0.f;
            #pragma unroll
            for (int z = 0; z < KSPLIT; z++) {
                const float* p = part + ((size_t)z * M + m) * N + n;
                s0 += p[0];
                s1 += p[1];
            }
            float x0 = fmaxf(s0 + __ldg(bias + n), 0.f);
            float x1 = fmaxf(s1 + __ldg(bias + n + 1), 0.f);
            __nv_bfloat16 h0 = __float2bfloat16(x0);
            __nv_bfloat16 h1 = __float2bfloat16(x1);
            __nv_bfloat16 l0 = __float2bfloat16(x0 - __bfloat162float(h0));
            __nv_bfloat16 l1 = __float2bfloat16(x1 - __bfloat162float(h1));
            *reinterpret_cast<uint32_t*>(Chi + (size_t)m * N + n) = pack_bf2(h0, h1);
            *reinterpret_cast<uint32_t*>(Clo + (size_t)m * N + n) = pack_bf2(l0, l1);
        }
        if (tid == 0) ticket[tileId] = 0;
    }
}

// Root projection
__global__ void proj_kernel(const __nv_bfloat16* __restrict__ hhi,
                            const __nv_bfloat16* __restrict__ hlo,
                            const float* __restrict__ Wp,
                            const float* __restrict__ bp,
                            float* __restrict__ out)
{
    const int w    = threadIdx.x >> 5;
    const int lane = threadIdx.x & 31;
    float s = 0.f;
    for (int k = lane; k < 512; k += 32) {
        const float hv = __bfloat162float(hhi[k]) + __bfloat162float(hlo[k]);
        s = fmaf(hv, Wp[w * 512 + k], s);
    }
    #pragma unroll
    for (int o = 16; o > 0; o >>= 1)
        s += __shfl_xor_sync(0xffffffffu, s, o);
    if (lane == 0) out[w] = s + bp[w];
}

extern "C" void kernel_launch(void* const* d_in, const int* in_sizes, int n_in,
                              void* d_out, int out_size)
{
    const float* leaf  = (const float*)d_in[0];
    const float* Wemb  = (const float*)d_in[1];
    const float* bemb  = (const float*)d_in[2];
    const float* Wcomb = (const float*)d_in[3];
    const float* bcomb = (const float*)d_in[4];
    const float* Wproj = (const float*)d_in[5];
    const float* bproj = (const float*)d_in[6];
    float* out = (float*)d_out;

    __half *leaf16, *We16, *Wc16, *P16, *Q16;
    __nv_bfloat16 *Wcb_h, *Wcb_l, *hB, *lB, *hC, *lC;
    float* part;
    unsigned* ticket;
    cudaGetSymbolAddress((void**)&leaf16, g_leaf16);
    cudaGetSymbolAddress((void**)&We16, g_We16);
    cudaGetSymbolAddress((void**)&Wc16, g_Wc16);
    cudaGetSymbolAddress((void**)&Wcb_h, g_Wcb_h);
    cudaGetSymbolAddress((void**)&Wcb_l, g_Wcb_l);
    cudaGetSymbolAddress((void**)&P16, g_P16);
    cudaGetSymbolAddress((void**)&Q16, g_Q16);
    cudaGetSymbolAddress((void**)&hB, g_hB);
    cudaGetSymbolAddress((void**)&lB, g_lB);
    cudaGetSymbolAddress((void**)&hC, g_hC);
    cudaGetSymbolAddress((void**)&lC, g_lC);
    cudaGetSymbolAddress((void**)&part, g_part);
    cudaGetSymbolAddress((void**)&ticket, g_ticket);

    cudaFuncSetAttribute(gemmh128,
                         cudaFuncAttributeMaxDynamicSharedMemorySize, SMEM128);
    cudaFuncSetAttribute(gemmh<0>,
                         cudaFuncAttributeMaxDynamicSharedMemorySize, SMEMH);
    cudaFuncSetAttribute(gemmh<1>,
                         cudaFuncAttributeMaxDynamicSharedMemorySize, SMEMH);
    cudaFuncSetAttribute(gemm_small_fused,
                         cudaFuncAttributeMaxDynamicSharedMemorySize, SMEM3);

    // ---- convert/split inputs ----
    conv_f16<<<4096, 256>>>((const float4*)leaf, (uint2*)leaf16, 8192 * 4096 / 4);
    conv_f16<<<512, 256>>>((const float4*)Wemb, (uint2*)We16, 512 * 4096 / 4);
    split_wc<<<128, 256>>>((const float4*)Wcomb, (uint2*)Wc16,
                           (uint2*)Wcb_h, (uint2*)Wcb_l, 512 * 1024 / 4);

    // ---- leaf -> P16 (128x128 tiles) ----
    {
        dim3 grid(512 / 128, 8192 / 128);
        gemmh128<<<grid, 256, SMEM128>>>(leaf16, We16, bemb, P16,
                                         8192, 512, 4096);
    }
    // ---- m = 4096 -> Q16 (128x128 tiles) ----
    {
        dim3 grid(512 / 128, 4096 / 128);
        gemmh128<<<grid, 256, SMEM128>>>(P16, Wc16, bcomb, Q16,
                                         4096, 512, 1024);
    }
    // ---- m = 2048 -> P16, m = 1024 -> bf16 pair (128x64 tiles) ----
    {
        dim3 grid(512 / 64, 2048 / 128);
        gemmh<0><<<grid, 256, SMEMH>>>(Q16, Wc16, bcomb,
                                       P16, nullptr, nullptr, 2048, 512, 1024);
    }
    {
        dim3 grid(512 / 64, 1024 / 128);
        gemmh<1><<<grid, 256, SMEMH>>>(P16, Wc16, bcomb,
                                       nullptr, hB, lB, 1024, 512, 1024);
    }

    // ---- tail m = 512..1: split-K with fused finalize ----
    __nv_bfloat16 *cur_h = hB, *cur_l = lB, *nxt_h = hC, *nxt_l = lC;
    for (int m = 512; m >= 1; m >>= 1) {
        dim3 grid(512 / 64, (m + 31) / 32, KSPLIT);
        gemm_small_fused<<<grid, 128, SMEM3>>>(cur_h, cur_l, Wcb_h, Wcb_l,
                                               bcomb, part, ticket,
                                               nxt_h, nxt_l, m, 512, 1024);
        __nv_bfloat16* t;
        t = cur_h; cur_h = nxt_h; nxt_h = t;
        t = cur_l; cur_l = nxt_l; nxt_l = t;
    }

    proj_kernel<<<1, 64>>>(cur_h, cur_l, Wproj, bproj, out);
}